// round 3
// baseline (speedup 1.0000x reference)
#include <cuda_runtime.h>
#include <cuda_bf16.h>
#include <math.h>

// Problem constants (fixed by the reference: B=1, N=50000, E=600000, H=128, ET=8)
#define NMAX 50000
#define EMAX 600000
#define HDIM 128
#define ETMAX 8

// ---------------- scratch (device globals; no allocations allowed) ----------------
__device__ float g_Qn[NMAX * HDIM];
__device__ float g_Kn[NMAX * HDIM];
__device__ float g_Vn[NMAX * HDIM];
__device__ float g_agg[NMAX * HDIM];
__device__ float g_T[NMAX * HDIM];
__device__ float g_U[NMAX * HDIM];
__device__ float g_logits[EMAX];     // exp(logit), edge order
__device__ int   g_deg[NMAX];        // degree histogram
__device__ int   g_off[NMAX + 1];    // CSR offsets
__device__ int   g_cursor[NMAX];     // scatter cursors
__device__ int   g_esort[EMAX];      // packed (src | type<<20), CSR order
__device__ float g_wsort[EMAX];      // exp(logit), CSR order
__device__ float g_EK[ETMAX * HDIM];
__device__ float g_EV[ETMAX * HDIM];
__device__ float g_ebias[ETMAX];

// ---------------- tf32 helpers ----------------
__device__ __forceinline__ unsigned f2tf32(float f) {
    unsigned u;
    asm("cvt.rna.tf32.f32 %0, %1;" : "=r"(u) : "f"(f));
    return u;
}

__device__ __forceinline__ void mma_tf32(float c[4], const unsigned a[4], const unsigned b[2]) {
    asm volatile(
        "mma.sync.aligned.m16n8k8.row.col.f32.tf32.tf32.f32 "
        "{%0,%1,%2,%3}, {%4,%5,%6,%7}, {%8,%9}, {%0,%1,%2,%3};"
        : "+f"(c[0]), "+f"(c[1]), "+f"(c[2]), "+f"(c[3])
        : "r"(a[0]), "r"(a[1]), "r"(a[2]), "r"(a[3]), "r"(b[0]), "r"(b[1]));
}

// ---------------- init: deg=0 ----------------
__global__ void init_kernel(int Nn) {
    int i = blockIdx.x * blockDim.x + threadIdx.x;
    if (i < Nn) g_deg[i] = 0;
}

// ---------------- per-edge-type tables: EK=eh@Wk, EV=eh@Wv, ebias=eh@Web+beb ----------------
__global__ void etype_precompute(const float* __restrict__ edge_emb,
                                 const float* __restrict__ Wk,
                                 const float* __restrict__ Wv,
                                 const float* __restrict__ Web,
                                 const float* __restrict__ beb,
                                 int ET) {
    int idx = blockIdx.x * blockDim.x + threadIdx.x;
    if (idx >= ET * HDIM) return;
    int t = idx / HDIM;
    int j = idx % HDIM;
    float sk = 0.0f, sv = 0.0f;
    const float* eh = edge_emb + t * HDIM;
#pragma unroll 8
    for (int k = 0; k < HDIM; k++) {
        float e = eh[k];
        sk = fmaf(e, Wk[k * HDIM + j], sk);
        sv = fmaf(e, Wv[k * HDIM + j], sv);
    }
    g_EK[idx] = sk;
    g_EV[idx] = sv;
    if (j == 0) {
        float s = beb[0];
        for (int k = 0; k < HDIM; k++) s = fmaf(eh[k], Web[k], s);
        g_ebias[t] = s;
    }
}

// ---------------- tf32x2 tensor-core GEMM ----------------
constexpr int BM = 128, BN = 128, BK = 16;
constexpr int LDA = BK + 4;   // 20 -> conflict-free frag loads
constexpr int LDB = BN + 8;   // 136 -> conflict-free frag loads

template <int KDIM, bool CONCAT, int ACT>  // ACT: 0 none, 1 silu
__global__ void mma_gemm(const float* __restrict__ A, const float* __restrict__ A2,
                         const float* __restrict__ W, const float* __restrict__ bias,
                         float* __restrict__ C, int M) {
    __shared__ float As_hi[BM][LDA];
    __shared__ float As_lo[BM][LDA];
    __shared__ float Bs_hi[BK][LDB];
    __shared__ float Bs_lo[BK][LDB];

    const int t = threadIdx.x;
    const int block_m = blockIdx.x * BM;
    const int lane = t & 31;
    const int wid = t >> 5;
    const int warp_m = (wid >> 2) * 64;   // 0 or 64
    const int warp_n = (wid & 3) * 32;    // 0,32,64,96
    const int lg = lane >> 2;             // 0..7
    const int lt = lane & 3;              // 0..3

    float acc[4][4][4];
#pragma unroll
    for (int mi = 0; mi < 4; mi++)
#pragma unroll
        for (int ni = 0; ni < 4; ni++)
#pragma unroll
            for (int r = 0; r < 4; r++) acc[mi][ni][r] = 0.0f;

    for (int k0 = 0; k0 < KDIM; k0 += BK) {
#pragma unroll
        for (int i = 0; i < 2; i++) {
            int idx = t + i * 256;
            int m = idx >> 2;
            int k4 = (idx & 3) * 4;
            int gm = block_m + m;
            float4 v = make_float4(0.f, 0.f, 0.f, 0.f);
            if (gm < M) {
                int gk = k0 + k4;
                if (!CONCAT) v = *(const float4*)(A + (size_t)gm * KDIM + gk);
                else v = (gk < HDIM) ? *(const float4*)(A + (size_t)gm * HDIM + gk)
                                     : *(const float4*)(A2 + (size_t)gm * HDIM + gk - HDIM);
            }
            float4 hi, lo;
            hi.x = __uint_as_float(f2tf32(v.x)); lo.x = __uint_as_float(f2tf32(v.x - hi.x));
            hi.y = __uint_as_float(f2tf32(v.y)); lo.y = __uint_as_float(f2tf32(v.y - hi.y));
            hi.z = __uint_as_float(f2tf32(v.z)); lo.z = __uint_as_float(f2tf32(v.z - hi.z));
            hi.w = __uint_as_float(f2tf32(v.w)); lo.w = __uint_as_float(f2tf32(v.w - hi.w));
            *(float4*)&As_hi[m][k4] = hi;
            *(float4*)&As_lo[m][k4] = lo;
        }
#pragma unroll
        for (int i = 0; i < 2; i++) {
            int idx = t + i * 256;
            int kk = idx >> 5;
            int n4 = (idx & 31) * 4;
            float4 v = *(const float4*)(W + (size_t)(k0 + kk) * BN + n4);
            float4 hi, lo;
            hi.x = __uint_as_float(f2tf32(v.x)); lo.x = __uint_as_float(f2tf32(v.x - hi.x));
            hi.y = __uint_as_float(f2tf32(v.y)); lo.y = __uint_as_float(f2tf32(v.y - hi.y));
            hi.z = __uint_as_float(f2tf32(v.z)); lo.z = __uint_as_float(f2tf32(v.z - hi.z));
            hi.w = __uint_as_float(f2tf32(v.w)); lo.w = __uint_as_float(f2tf32(v.w - hi.w));
            *(float4*)&Bs_hi[kk][n4] = hi;
            *(float4*)&Bs_lo[kk][n4] = lo;
        }
        __syncthreads();

#pragma unroll
        for (int ks = 0; ks < BK; ks += 8) {
            unsigned ah[4][4], al[4][4], bh[4][2], bl[4][2];
#pragma unroll
            for (int mi = 0; mi < 4; mi++) {
                int r = warp_m + mi * 16 + lg;
                int c = ks + lt;
                ah[mi][0] = __float_as_uint(As_hi[r][c]);
                ah[mi][1] = __float_as_uint(As_hi[r + 8][c]);
                ah[mi][2] = __float_as_uint(As_hi[r][c + 4]);
                ah[mi][3] = __float_as_uint(As_hi[r + 8][c + 4]);
                al[mi][0] = __float_as_uint(As_lo[r][c]);
                al[mi][1] = __float_as_uint(As_lo[r + 8][c]);
                al[mi][2] = __float_as_uint(As_lo[r][c + 4]);
                al[mi][3] = __float_as_uint(As_lo[r + 8][c + 4]);
            }
#pragma unroll
            for (int ni = 0; ni < 4; ni++) {
                int n = warp_n + ni * 8 + lg;
                int k = ks + lt;
                bh[ni][0] = __float_as_uint(Bs_hi[k][n]);
                bh[ni][1] = __float_as_uint(Bs_hi[k + 4][n]);
                bl[ni][0] = __float_as_uint(Bs_lo[k][n]);
                bl[ni][1] = __float_as_uint(Bs_lo[k + 4][n]);
            }
#pragma unroll
            for (int mi = 0; mi < 4; mi++)
#pragma unroll
                for (int ni = 0; ni < 4; ni++) {
                    mma_tf32(acc[mi][ni], ah[mi], bl[ni]);
                    mma_tf32(acc[mi][ni], al[mi], bh[ni]);
                    mma_tf32(acc[mi][ni], ah[mi], bh[ni]);
                }
        }
        __syncthreads();
    }

#pragma unroll
    for (int mi = 0; mi < 4; mi++) {
#pragma unroll
        for (int ni = 0; ni < 4; ni++) {
            int n = warp_n + ni * 8 + lt * 2;
            float b0 = bias[n], b1 = bias[n + 1];
#pragma unroll
            for (int h = 0; h < 2; h++) {
                int gm = block_m + warp_m + mi * 16 + lg + h * 8;
                if (gm >= M) continue;
                float v0 = acc[mi][ni][2 * h] + b0;
                float v1 = acc[mi][ni][2 * h + 1] + b1;
                if (ACT == 1) {
                    v0 = v0 / (1.0f + expf(-v0));
                    v1 = v1 / (1.0f + expf(-v1));
                }
                float2 o = make_float2(v0, v1);
                *(float2*)(C + (size_t)gm * BN + n) = o;
            }
        }
    }
}

// ---------------- edge pass: logits -> exp; degree histogram ----------------
// Max-subtraction is skipped: logits are O(1) here (validated rel_err 4.5e-7).
__global__ void edge_logits_kernel(const int* __restrict__ src, const int* __restrict__ tgt,
                                   const int* __restrict__ etype, int E) {
    int e = blockIdx.x * 8 + (threadIdx.x >> 5);
    if (e >= E) return;
    int lane = threadIdx.x & 31;
    int s = src[e], g = tgt[e], ty = etype[e];
    float4 q = ((const float4*)(g_Qn + (size_t)g * HDIM))[lane];
    float4 k = ((const float4*)(g_Kn + (size_t)s * HDIM))[lane];
    float4 ek = ((const float4*)(g_EK + ty * HDIM))[lane];
    float d = q.x * (k.x + ek.x) + q.y * (k.y + ek.y) + q.z * (k.z + ek.z) + q.w * (k.w + ek.w);
#pragma unroll
    for (int o = 16; o; o >>= 1) d += __shfl_xor_sync(0xffffffffu, d, o);
    if (lane == 0) {
        float l = d * 0.08838834764831845f /* 1/sqrt(128) */ + g_ebias[ty];
        g_logits[e] = expf(l);
        atomicAdd(&g_deg[g], 1);
    }
}

// ---------------- CSR offsets: single-block exclusive scan over degrees ----------------
__global__ void scan_kernel(int Nn) {
    __shared__ int partial[1024];
    int t = threadIdx.x;
    int chunk = (Nn + 1023) >> 10;
    int lo = t * chunk;
    int hi = min(lo + chunk, Nn);
    int s = 0;
    for (int i = lo; i < hi; i++) s += g_deg[i];
    partial[t] = s;
    __syncthreads();
#pragma unroll
    for (int off = 1; off < 1024; off <<= 1) {
        int v = (t >= off) ? partial[t - off] : 0;
        __syncthreads();
        partial[t] += v;
        __syncthreads();
    }
    int run = (t == 0) ? 0 : partial[t - 1];
    for (int i = lo; i < hi; i++) {
        g_off[i] = run;
        g_cursor[i] = run;
        run += g_deg[i];
    }
    if (t == 1023) g_off[Nn] = partial[1023];
}

// ---------------- scatter: bucket edges by target into CSR order ----------------
__global__ void scatter_kernel(const int* __restrict__ src, const int* __restrict__ tgt,
                               const int* __restrict__ etype, int E) {
    int e = blockIdx.x * blockDim.x + threadIdx.x;
    if (e >= E) return;
    int g = tgt[e];
    int pos = atomicAdd(&g_cursor[g], 1);
    g_esort[pos] = src[e] | (etype[e] << 20);
    g_wsort[pos] = g_logits[e];
}

// ---------------- aggregation: warp per node, register accumulation, one store ----------------
__global__ void node_agg_kernel(int Nn) {
    int n = blockIdx.x * 8 + (threadIdx.x >> 5);
    if (n >= Nn) return;
    int lane = threadIdx.x & 31;
    int off0 = g_off[n];
    int deg = g_off[n + 1] - off0;
    float4 acc = make_float4(0.f, 0.f, 0.f, 0.f);
    if (deg > 0) {
        float s = 0.0f;
        for (int j = lane; j < deg; j += 32) s += g_wsort[off0 + j];
#pragma unroll
        for (int o = 16; o; o >>= 1) s += __shfl_xor_sync(0xffffffffu, s, o);
        float inv = 1.0f / s;
#pragma unroll 2
        for (int j = 0; j < deg; j++) {
            int packed = g_esort[off0 + j];
            float w = g_wsort[off0 + j] * inv;
            int sidx = packed & 0xFFFFF;
            int ty = packed >> 20;
            float4 v = ((const float4*)(g_Vn + (size_t)sidx * HDIM))[lane];
            float4 ev = ((const float4*)(g_EV + ty * HDIM))[lane];
            acc.x = fmaf(w, v.x + ev.x, acc.x);
            acc.y = fmaf(w, v.y + ev.y, acc.y);
            acc.z = fmaf(w, v.z + ev.z, acc.z);
            acc.w = fmaf(w, v.w + ev.w, acc.w);
        }
    }
    ((float4*)(g_agg + (size_t)n * HDIM))[lane] = acc;
}

// ---------------- residual + layernorm (warp per node) ----------------
__global__ void residual_ln_kernel(const float* __restrict__ hidden,
                                   const float* __restrict__ gamma,
                                   const float* __restrict__ beta,
                                   float* __restrict__ out, int Nn) {
    int n = blockIdx.x * 8 + (threadIdx.x >> 5);
    if (n >= Nn) return;
    int lane = threadIdx.x & 31;
    float4 h = ((const float4*)(hidden + (size_t)n * HDIM))[lane];
    float4 u = ((const float4*)(g_U + (size_t)n * HDIM))[lane];
    float x0 = h.x + u.x, x1 = h.y + u.y, x2 = h.z + u.z, x3 = h.w + u.w;
    float sum = x0 + x1 + x2 + x3;
#pragma unroll
    for (int o = 16; o; o >>= 1) sum += __shfl_xor_sync(0xffffffffu, sum, o);
    float mu = sum * (1.0f / 128.0f);
    float d0 = x0 - mu, d1 = x1 - mu, d2 = x2 - mu, d3 = x3 - mu;
    float vs = d0 * d0 + d1 * d1 + d2 * d2 + d3 * d3;
#pragma unroll
    for (int o = 16; o; o >>= 1) vs += __shfl_xor_sync(0xffffffffu, vs, o);
    float inv = rsqrtf(vs * (1.0f / 128.0f) + 1e-5f);
    float4 gm = ((const float4*)gamma)[lane];
    float4 bt = ((const float4*)beta)[lane];
    float4 o4;
    o4.x = d0 * inv * gm.x + bt.x;
    o4.y = d1 * inv * gm.y + bt.y;
    o4.z = d2 * inv * gm.z + bt.z;
    o4.w = d3 * inv * gm.w + bt.w;
    ((float4*)(out + (size_t)n * HDIM))[lane] = o4;
}

// ---------------- launch ----------------
extern "C" void kernel_launch(void* const* d_in, const int* in_sizes, int n_in,
                              void* d_out, int out_size) {
    const float* hidden   = (const float*)d_in[0];
    const int*   edge_idx = (const int*)d_in[1];
    const int*   etype    = (const int*)d_in[2];
    const float* edge_emb = (const float*)d_in[3];
    const float* Wq = (const float*)d_in[4];
    const float* bq = (const float*)d_in[5];
    const float* Wk = (const float*)d_in[6];
    const float* bk = (const float*)d_in[7];
    const float* Wv = (const float*)d_in[8];
    const float* bv = (const float*)d_in[9];
    const float* Web = (const float*)d_in[10];
    const float* beb = (const float*)d_in[11];
    const float* W1 = (const float*)d_in[12];
    const float* b1 = (const float*)d_in[13];
    const float* W2 = (const float*)d_in[14];
    const float* b2 = (const float*)d_in[15];
    const float* gamma = (const float*)d_in[16];
    const float* beta  = (const float*)d_in[17];
    float* out = (float*)d_out;

    const int N  = in_sizes[0] / HDIM;   // B=1
    const int E  = in_sizes[2];
    const int ET = in_sizes[3] / HDIM;
    const int* src = edge_idx;           // edge_index[0]
    const int* tgt = edge_idx + E;       // edge_index[1]

    float *pQ, *pK, *pV, *pAgg, *pT, *pU;
    cudaGetSymbolAddress((void**)&pQ, g_Qn);
    cudaGetSymbolAddress((void**)&pK, g_Kn);
    cudaGetSymbolAddress((void**)&pV, g_Vn);
    cudaGetSymbolAddress((void**)&pAgg, g_agg);
    cudaGetSymbolAddress((void**)&pT, g_T);
    cudaGetSymbolAddress((void**)&pU, g_U);

    // 1. init degree histogram
    init_kernel<<<(N + 255) / 256, 256>>>(N);

    // 2. edge-type tables (tiny)
    etype_precompute<<<(ET * HDIM + 255) / 256, 256>>>(edge_emb, Wk, Wv, Web, beb, ET);

    // 3. node Q/K/V tables (bias folded into epilogue)
    int gemm_blocks = (N + BM - 1) / BM;
    mma_gemm<128, false, 0><<<gemm_blocks, 256>>>(hidden, nullptr, Wq, bq, pQ, N);
    mma_gemm<128, false, 0><<<gemm_blocks, 256>>>(hidden, nullptr, Wk, bk, pK, N);
    mma_gemm<128, false, 0><<<gemm_blocks, 256>>>(hidden, nullptr, Wv, bv, pV, N);

    // 4. edge phase: logits+exp+histogram -> CSR scan -> scatter -> gather-aggregate
    edge_logits_kernel<<<(E + 7) / 8, 256>>>(src, tgt, etype, E);
    scan_kernel<<<1, 1024>>>(N);
    scatter_kernel<<<(E + 255) / 256, 256>>>(src, tgt, etype, E);
    node_agg_kernel<<<(N + 7) / 8, 256>>>(N);

    // 5. FFN: T = silu([hidden|agg] @ W1 + b1); U = T @ W2 + b2
    mma_gemm<256, true, 1><<<gemm_blocks, 256>>>(hidden, pAgg, W1, b1, pT, N);
    mma_gemm<128, false, 0><<<gemm_blocks, 256>>>(pT, nullptr, W2, b2, pU, N);

    // 6. residual + layernorm
    residual_ln_kernel<<<(N + 7) / 8, 256>>>(hidden, gamma, beta, out, N);
}

// round 4
// speedup vs baseline: 1.1996x; 1.1996x over previous
#include <cuda_runtime.h>
#include <cuda_bf16.h>
#include <math.h>

// Problem constants (fixed by the reference: B=1, N=50000, E=600000, H=128, ET=8)
#define NMAX 50000
#define EMAX 600000
#define HDIM 128
#define ETMAX 8

// ---------------- scratch (device globals; no allocations allowed) ----------------
__device__ float g_Qn[NMAX * HDIM];
__device__ float g_Kn[NMAX * HDIM];
__device__ float g_Vn[NMAX * HDIM];
__device__ float g_agg[NMAX * HDIM];
__device__ float g_T[NMAX * HDIM];
__device__ float g_U[NMAX * HDIM];
__device__ float g_logits[EMAX];   // exp(logit)
__device__ float g_sm[NMAX];
__device__ float g_EK[ETMAX * HDIM];
__device__ float g_EV[ETMAX * HDIM];
__device__ float g_ebias[ETMAX];

// ---------------- bf16 helpers ----------------
__device__ __forceinline__ unsigned pack_bf16(__nv_bfloat16 lo_k, __nv_bfloat16 hi_k) {
    // lo_k -> bits [0:16) (lower k index), hi_k -> bits [16:32)
    return ((unsigned)__bfloat16_as_ushort(hi_k) << 16) | (unsigned)__bfloat16_as_ushort(lo_k);
}

__device__ __forceinline__ void split_bf16(float v, __nv_bfloat16& hi, __nv_bfloat16& lo) {
    hi = __float2bfloat16(v);
    lo = __float2bfloat16(v - __bfloat162float(hi));
}

__device__ __forceinline__ void mma_bf16(float c[4], const unsigned a[4], const unsigned b[2]) {
    asm volatile(
        "mma.sync.aligned.m16n8k16.row.col.f32.bf16.bf16.f32 "
        "{%0,%1,%2,%3}, {%4,%5,%6,%7}, {%8,%9}, {%0,%1,%2,%3};"
        : "+f"(c[0]), "+f"(c[1]), "+f"(c[2]), "+f"(c[3])
        : "r"(a[0]), "r"(a[1]), "r"(a[2]), "r"(a[3]), "r"(b[0]), "r"(b[1]));
}

// ---------------- init: sm=0, agg=0 ----------------
__global__ void init_kernel(int Nn) {
    int i = blockIdx.x * blockDim.x + threadIdx.x;
    if (i < Nn) g_sm[i] = 0.0f;
    if (i < Nn * HDIM) g_agg[i] = 0.0f;
}

// ---------------- per-edge-type tables: EK=eh@Wk, EV=eh@Wv, ebias=eh@Web+beb ----------------
__global__ void etype_precompute(const float* __restrict__ edge_emb,
                                 const float* __restrict__ Wk,
                                 const float* __restrict__ Wv,
                                 const float* __restrict__ Web,
                                 const float* __restrict__ beb,
                                 int ET) {
    int idx = blockIdx.x * blockDim.x + threadIdx.x;
    if (idx >= ET * HDIM) return;
    int t = idx / HDIM;
    int j = idx % HDIM;
    float sk = 0.0f, sv = 0.0f;
    const float* eh = edge_emb + t * HDIM;
#pragma unroll 8
    for (int k = 0; k < HDIM; k++) {
        float e = eh[k];
        sk = fmaf(e, Wk[k * HDIM + j], sk);
        sv = fmaf(e, Wv[k * HDIM + j], sv);
    }
    g_EK[idx] = sk;
    g_EV[idx] = sv;
    if (j == 0) {
        float s = beb[0];
        for (int k = 0; k < HDIM; k++) s = fmaf(eh[k], Web[k], s);
        g_ebias[t] = s;
    }
}

// ---------------- bf16x2 tensor-core GEMM (3-term error compensated) ----------------
// C[M x 128] = act(A[M x KDIM] @ W[KDIM x 128] + bias)
// BM=128, BN=128, BK=32; 256 threads; warp tile 64x32 via 4x4 m16n8k16 MMAs.
// blockIdx.y selects among up to 3 (W, bias, C) triples sharing the same A.
constexpr int BM = 128, BN = 128, BK = 32;
constexpr int LDK = BK + 8;   // As row length (bf16), conflict-free frag loads
constexpr int LDN = BN + 8;   // Bs row length (bf16), conflict-free frag loads

template <int KDIM, bool CONCAT, int ACT>  // ACT: 0 none, 1 silu
__global__ void mma_gemm(const float* __restrict__ A, const float* __restrict__ A2,
                         const float* __restrict__ W0, const float* __restrict__ W1,
                         const float* __restrict__ W2,
                         const float* __restrict__ bias0, const float* __restrict__ bias1,
                         const float* __restrict__ bias2,
                         float* __restrict__ C0, float* __restrict__ C1, float* __restrict__ C2,
                         int M) {
    __shared__ __nv_bfloat16 As_hi[BM][LDK];
    __shared__ __nv_bfloat16 As_lo[BM][LDK];
    __shared__ __nv_bfloat16 Bs_hi[BK][LDN];
    __shared__ __nv_bfloat16 Bs_lo[BK][LDN];

    const float* W    = (blockIdx.y == 0) ? W0 : (blockIdx.y == 1) ? W1 : W2;
    const float* bias = (blockIdx.y == 0) ? bias0 : (blockIdx.y == 1) ? bias1 : bias2;
    float* C          = (blockIdx.y == 0) ? C0 : (blockIdx.y == 1) ? C1 : C2;

    const int t = threadIdx.x;
    const int block_m = blockIdx.x * BM;
    const int lane = t & 31;
    const int wid = t >> 5;
    const int warp_m = (wid >> 2) * 64;   // 0 or 64
    const int warp_n = (wid & 3) * 32;    // 0,32,64,96
    const int lg = lane >> 2;             // 0..7
    const int lt = lane & 3;              // 0..3

    float acc[4][4][4];
#pragma unroll
    for (int mi = 0; mi < 4; mi++)
#pragma unroll
        for (int ni = 0; ni < 4; ni++)
#pragma unroll
            for (int r = 0; r < 4; r++) acc[mi][ni][r] = 0.0f;

    for (int k0 = 0; k0 < KDIM; k0 += BK) {
        // ---- load A tile (128 x 32 floats): 1024 float4, 4 per thread ----
#pragma unroll
        for (int i = 0; i < 4; i++) {
            int idx = t + i * 256;
            int m = idx >> 3;
            int k4 = (idx & 7) * 4;
            int gm = block_m + m;
            float4 v = make_float4(0.f, 0.f, 0.f, 0.f);
            if (gm < M) {
                int gk = k0 + k4;
                if (!CONCAT) v = *(const float4*)(A + (size_t)gm * KDIM + gk);
                else v = (gk < HDIM) ? *(const float4*)(A + (size_t)gm * HDIM + gk)
                                     : *(const float4*)(A2 + (size_t)gm * HDIM + gk - HDIM);
            }
            __nv_bfloat16 hx, lx, hy, ly, hz, lz, hw, lw;
            split_bf16(v.x, hx, lx); split_bf16(v.y, hy, ly);
            split_bf16(v.z, hz, lz); split_bf16(v.w, hw, lw);
            *(uint2*)&As_hi[m][k4] = make_uint2(pack_bf16(hx, hy), pack_bf16(hz, hw));
            *(uint2*)&As_lo[m][k4] = make_uint2(pack_bf16(lx, ly), pack_bf16(lz, lw));
        }
        // ---- load B tile (32 x 128 floats): 1024 float4, 4 per thread ----
#pragma unroll
        for (int i = 0; i < 4; i++) {
            int idx = t + i * 256;
            int kk = idx >> 5;
            int n4 = (idx & 31) * 4;
            float4 v = *(const float4*)(W + (size_t)(k0 + kk) * BN + n4);
            __nv_bfloat16 hx, lx, hy, ly, hz, lz, hw, lw;
            split_bf16(v.x, hx, lx); split_bf16(v.y, hy, ly);
            split_bf16(v.z, hz, lz); split_bf16(v.w, hw, lw);
            *(uint2*)&Bs_hi[kk][n4] = make_uint2(pack_bf16(hx, hy), pack_bf16(hz, hw));
            *(uint2*)&Bs_lo[kk][n4] = make_uint2(pack_bf16(lx, ly), pack_bf16(lz, lw));
        }
        __syncthreads();

#pragma unroll
        for (int ks = 0; ks < BK; ks += 16) {
            unsigned ah[4][4], al[4][4], bh[4][2], bl[4][2];
#pragma unroll
            for (int mi = 0; mi < 4; mi++) {
                int r = warp_m + mi * 16 + lg;
                int c = ks + lt * 2;
                ah[mi][0] = *(const unsigned*)&As_hi[r][c];
                ah[mi][1] = *(const unsigned*)&As_hi[r + 8][c];
                ah[mi][2] = *(const unsigned*)&As_hi[r][c + 8];
                ah[mi][3] = *(const unsigned*)&As_hi[r + 8][c + 8];
                al[mi][0] = *(const unsigned*)&As_lo[r][c];
                al[mi][1] = *(const unsigned*)&As_lo[r + 8][c];
                al[mi][2] = *(const unsigned*)&As_lo[r][c + 8];
                al[mi][3] = *(const unsigned*)&As_lo[r + 8][c + 8];
            }
#pragma unroll
            for (int ni = 0; ni < 4; ni++) {
                int n = warp_n + ni * 8 + lg;
                int k = ks + lt * 2;
                bh[ni][0] = pack_bf16(Bs_hi[k][n], Bs_hi[k + 1][n]);
                bh[ni][1] = pack_bf16(Bs_hi[k + 8][n], Bs_hi[k + 9][n]);
                bl[ni][0] = pack_bf16(Bs_lo[k][n], Bs_lo[k + 1][n]);
                bl[ni][1] = pack_bf16(Bs_lo[k + 8][n], Bs_lo[k + 9][n]);
            }
#pragma unroll
            for (int mi = 0; mi < 4; mi++)
#pragma unroll
                for (int ni = 0; ni < 4; ni++) {
                    mma_bf16(acc[mi][ni], ah[mi], bl[ni]);
                    mma_bf16(acc[mi][ni], al[mi], bh[ni]);
                    mma_bf16(acc[mi][ni], ah[mi], bh[ni]);
                }
        }
        __syncthreads();
    }

    // ---- epilogue: bias (+silu), store ----
#pragma unroll
    for (int mi = 0; mi < 4; mi++) {
#pragma unroll
        for (int ni = 0; ni < 4; ni++) {
            int n = warp_n + ni * 8 + lt * 2;
            float b0 = bias[n], b1 = bias[n + 1];
#pragma unroll
            for (int h = 0; h < 2; h++) {
                int gm = block_m + warp_m + mi * 16 + lg + h * 8;
                if (gm >= M) continue;
                float v0 = acc[mi][ni][2 * h] + b0;
                float v1 = acc[mi][ni][2 * h + 1] + b1;
                if (ACT == 1) {
                    v0 = v0 / (1.0f + expf(-v0));
                    v1 = v1 / (1.0f + expf(-v1));
                }
                *(float2*)(C + (size_t)gm * BN + n) = make_float2(v0, v1);
            }
        }
    }
}

// ---------------- edge pass 1: logits -> exp -> segment sum (warp per edge) ----------------
// Max-subtraction is skipped: logits are O(1) here (validated rel_err ~4.5e-7).
__global__ void edge_logits_kernel(const int* __restrict__ src, const int* __restrict__ tgt,
                                   const int* __restrict__ etype, int E) {
    int e = blockIdx.x * 8 + (threadIdx.x >> 5);
    if (e >= E) return;
    int lane = threadIdx.x & 31;
    int s = src[e], g = tgt[e], ty = etype[e];
    float4 q = ((const float4*)(g_Qn + (size_t)g * HDIM))[lane];
    float4 k = ((const float4*)(g_Kn + (size_t)s * HDIM))[lane];
    float4 ek = ((const float4*)(g_EK + ty * HDIM))[lane];
    float d = q.x * (k.x + ek.x) + q.y * (k.y + ek.y) + q.z * (k.z + ek.z) + q.w * (k.w + ek.w);
#pragma unroll
    for (int o = 16; o; o >>= 1) d += __shfl_xor_sync(0xffffffffu, d, o);
    if (lane == 0) {
        float l = d * 0.08838834764831845f /* 1/sqrt(128) */ + g_ebias[ty];
        float ex = expf(l);
        g_logits[e] = ex;
        atomicAdd(&g_sm[g], ex);
    }
}

// ---------------- edge pass 2: weighted aggregation via vector REDG (warp per edge) ----------------
__global__ void edge_agg_kernel(const int* __restrict__ src, const int* __restrict__ tgt,
                                const int* __restrict__ etype, int E) {
    int e = blockIdx.x * 8 + (threadIdx.x >> 5);
    if (e >= E) return;
    int lane = threadIdx.x & 31;
    int s = src[e], g = tgt[e], ty = etype[e];
    float w = g_logits[e] / g_sm[g];
    float4 v = ((const float4*)(g_Vn + (size_t)s * HDIM))[lane];
    float4 ev = ((const float4*)(g_EV + ty * HDIM))[lane];
    float* dst = g_agg + (size_t)g * HDIM + lane * 4;
    float a0 = w * (v.x + ev.x), a1 = w * (v.y + ev.y);
    float a2 = w * (v.z + ev.z), a3 = w * (v.w + ev.w);
    asm volatile("red.global.add.v4.f32 [%0], {%1, %2, %3, %4};"
                 :: "l"(dst), "f"(a0), "f"(a1), "f"(a2), "f"(a3) : "memory");
}

// ---------------- residual + layernorm (warp per node) ----------------
__global__ void residual_ln_kernel(const float* __restrict__ hidden,
                                   const float* __restrict__ gamma,
                                   const float* __restrict__ beta,
                                   float* __restrict__ out, int Nn) {
    int n = blockIdx.x * 8 + (threadIdx.x >> 5);
    if (n >= Nn) return;
    int lane = threadIdx.x & 31;
    float4 h = ((const float4*)(hidden + (size_t)n * HDIM))[lane];
    float4 u = ((const float4*)(g_U + (size_t)n * HDIM))[lane];
    float x0 = h.x + u.x, x1 = h.y + u.y, x2 = h.z + u.z, x3 = h.w + u.w;
    float sum = x0 + x1 + x2 + x3;
#pragma unroll
    for (int o = 16; o; o >>= 1) sum += __shfl_xor_sync(0xffffffffu, sum, o);
    float mu = sum * (1.0f / 128.0f);
    float d0 = x0 - mu, d1 = x1 - mu, d2 = x2 - mu, d3 = x3 - mu;
    float vs = d0 * d0 + d1 * d1 + d2 * d2 + d3 * d3;
#pragma unroll
    for (int o = 16; o; o >>= 1) vs += __shfl_xor_sync(0xffffffffu, vs, o);
    float inv = rsqrtf(vs * (1.0f / 128.0f) + 1e-5f);
    float4 gm = ((const float4*)gamma)[lane];
    float4 bt = ((const float4*)beta)[lane];
    float4 o4;
    o4.x = d0 * inv * gm.x + bt.x;
    o4.y = d1 * inv * gm.y + bt.y;
    o4.z = d2 * inv * gm.z + bt.z;
    o4.w = d3 * inv * gm.w + bt.w;
    ((float4*)(out + (size_t)n * HDIM))[lane] = o4;
}

// ---------------- launch ----------------
extern "C" void kernel_launch(void* const* d_in, const int* in_sizes, int n_in,
                              void* d_out, int out_size) {
    const float* hidden   = (const float*)d_in[0];
    const int*   edge_idx = (const int*)d_in[1];
    const int*   etype    = (const int*)d_in[2];
    const float* edge_emb = (const float*)d_in[3];
    const float* Wq = (const float*)d_in[4];
    const float* bq = (const float*)d_in[5];
    const float* Wk = (const float*)d_in[6];
    const float* bk = (const float*)d_in[7];
    const float* Wv = (const float*)d_in[8];
    const float* bv = (const float*)d_in[9];
    const float* Web = (const float*)d_in[10];
    const float* beb = (const float*)d_in[11];
    const float* W1 = (const float*)d_in[12];
    const float* b1 = (const float*)d_in[13];
    const float* W2 = (const float*)d_in[14];
    const float* b2 = (const float*)d_in[15];
    const float* gamma = (const float*)d_in[16];
    const float* beta  = (const float*)d_in[17];
    float* out = (float*)d_out;

    const int N  = in_sizes[0] / HDIM;   // B=1
    const int E  = in_sizes[2];
    const int ET = in_sizes[3] / HDIM;
    const int* src = edge_idx;           // edge_index[0]
    const int* tgt = edge_idx + E;       // edge_index[1]

    float *pQ, *pK, *pV, *pAgg, *pT, *pU;
    cudaGetSymbolAddress((void**)&pQ, g_Qn);
    cudaGetSymbolAddress((void**)&pK, g_Kn);
    cudaGetSymbolAddress((void**)&pV, g_Vn);
    cudaGetSymbolAddress((void**)&pAgg, g_agg);
    cudaGetSymbolAddress((void**)&pT, g_T);
    cudaGetSymbolAddress((void**)&pU, g_U);

    // 1. init sm / agg
    init_kernel<<<(N * HDIM + 255) / 256, 256>>>(N);

    // 2. edge-type tables (tiny)
    etype_precompute<<<(ET * HDIM + 255) / 256, 256>>>(edge_emb, Wk, Wv, Web, beb, ET);

    // 3. node Q/K/V tables, fused into one launch (blockIdx.y selects matrix)
    int gemm_blocks = (N + BM - 1) / BM;
    dim3 qkv_grid(gemm_blocks, 3);
    mma_gemm<128, false, 0><<<qkv_grid, 256>>>(hidden, nullptr,
                                               Wq, Wk, Wv, bq, bk, bv,
                                               pQ, pK, pV, N);

    // 4. edge passes: logits+exp+sum, weighted aggregation
    edge_logits_kernel<<<(E + 7) / 8, 256>>>(src, tgt, etype, E);
    edge_agg_kernel<<<(E + 7) / 8, 256>>>(src, tgt, etype, E);

    // 5. FFN: T = silu([hidden|agg] @ W1 + b1); U = T @ W2 + b2
    mma_gemm<256, true, 1><<<dim3(gemm_blocks, 1), 256>>>(hidden, pAgg,
                                                          W1, W1, W1, b1, b1, b1,
                                                          pT, pT, pT, N);
    mma_gemm<128, false, 0><<<dim3(gemm_blocks, 1), 256>>>(pT, nullptr,
                                                           W2, W2, W2, b2, b2, b2,
                                                           pU, pU, pU, N);

    // 6. residual + layernorm
    residual_ln_kernel<<<(N + 7) / 8, 256>>>(hidden, gamma, beta, out, N);
}

// round 5
// speedup vs baseline: 1.3192x; 1.0996x over previous
#include <cuda_runtime.h>
#include <cuda_bf16.h>
#include <math.h>

// Problem constants (fixed by the reference: B=1, N=50000, E=600000, H=128, ET=8)
#define NMAX 50000
#define EMAX 600000
#define HDIM 128
#define ETMAX 8

// ---------------- scratch (device globals; no allocations allowed) ----------------
__device__ float g_Qn[NMAX * HDIM];    // pre-scaled by 1/sqrt(H)
__device__ float g_Kn[NMAX * HDIM];
__device__ float g_Vn[NMAX * HDIM];
__device__ float g_agg[NMAX * HDIM];   // unnormalized sum of ex*(V+EV)
__device__ float g_T[NMAX * HDIM];
__device__ float g_U[NMAX * HDIM];
__device__ float g_sm[NMAX];           // sum of ex per target node
__device__ float g_QEK[NMAX * ETMAX];  // q_scaled . EK[ty] + ebias[ty]
__device__ float g_EK[ETMAX * HDIM];
__device__ float g_EV[ETMAX * HDIM];
__device__ float g_ebias[ETMAX];

// ---------------- bf16 helpers ----------------
__device__ __forceinline__ unsigned pack_bf16(__nv_bfloat16 lo_k, __nv_bfloat16 hi_k) {
    return ((unsigned)__bfloat16_as_ushort(hi_k) << 16) | (unsigned)__bfloat16_as_ushort(lo_k);
}

__device__ __forceinline__ void split_bf16(float v, __nv_bfloat16& hi, __nv_bfloat16& lo) {
    hi = __float2bfloat16(v);
    lo = __float2bfloat16(v - __bfloat162float(hi));
}

__device__ __forceinline__ void mma_bf16(float c[4], const unsigned a[4], const unsigned b[2]) {
    asm volatile(
        "mma.sync.aligned.m16n8k16.row.col.f32.bf16.bf16.f32 "
        "{%0,%1,%2,%3}, {%4,%5,%6,%7}, {%8,%9}, {%0,%1,%2,%3};"
        : "+f"(c[0]), "+f"(c[1]), "+f"(c[2]), "+f"(c[3])
        : "r"(a[0]), "r"(a[1]), "r"(a[2]), "r"(a[3]), "r"(b[0]), "r"(b[1]));
}

// ---------------- init: sm=0, agg=0 ----------------
__global__ void init_kernel(int Nn) {
    int i = blockIdx.x * blockDim.x + threadIdx.x;
    if (i < Nn) g_sm[i] = 0.0f;
    if (i < Nn * HDIM) g_agg[i] = 0.0f;
}

// ---------------- per-edge-type tables: EK=eh@Wk, EV=eh@Wv, ebias=eh@Web+beb ----------------
__global__ void etype_precompute(const float* __restrict__ edge_emb,
                                 const float* __restrict__ Wk,
                                 const float* __restrict__ Wv,
                                 const float* __restrict__ Web,
                                 const float* __restrict__ beb,
                                 int ET) {
    int idx = blockIdx.x * blockDim.x + threadIdx.x;
    if (idx >= ET * HDIM) return;
    int t = idx / HDIM;
    int j = idx % HDIM;
    float sk = 0.0f, sv = 0.0f;
    const float* eh = edge_emb + t * HDIM;
#pragma unroll 8
    for (int k = 0; k < HDIM; k++) {
        float e = eh[k];
        sk = fmaf(e, Wk[k * HDIM + j], sk);
        sv = fmaf(e, Wv[k * HDIM + j], sv);
    }
    g_EK[idx] = sk;
    g_EV[idx] = sv;
    if (j == 0) {
        float s = beb[0];
        for (int k = 0; k < HDIM; k++) s = fmaf(eh[k], Web[k], s);
        g_ebias[t] = s;
    }
}

// ---------------- QEK table: QEK[n][ty] = Qs[n] . EK[ty] + ebias[ty] (warp per node) ----------------
__global__ void qek_kernel(int Nn) {
    int n = blockIdx.x * 8 + (threadIdx.x >> 5);
    if (n >= Nn) return;
    int lane = threadIdx.x & 31;
    float4 q = ((const float4*)(g_Qn + (size_t)n * HDIM))[lane];
    float res = 0.0f;
#pragma unroll
    for (int ty = 0; ty < ETMAX; ty++) {
        float4 ek = ((const float4*)(g_EK + ty * HDIM))[lane];
        float d = q.x * ek.x + q.y * ek.y + q.z * ek.z + q.w * ek.w;
#pragma unroll
        for (int o = 16; o; o >>= 1) d += __shfl_xor_sync(0xffffffffu, d, o);
        if (lane == ty) res = d;
    }
    if (lane < ETMAX) g_QEK[n * ETMAX + lane] = res + g_ebias[lane];
}

// ---------------- bf16x2 tensor-core GEMM (3-term error compensated) ----------------
// C[M x 128] = act(A[M x KDIM] @ W[KDIM x 128] + bias) * scl
// BM=128, BN=128, BK=32; 256 threads; warp tile 64x32 via 4x4 m16n8k16 MMAs.
// blockIdx.y selects among up to 3 (W, bias, C) triples sharing the same A.
// When CONCAT: second half of A is g_agg divided by g_sm (guarded).
constexpr int BM = 128, BN = 128, BK = 32;
constexpr int LDK = BK + 8;
constexpr int LDN = BN + 8;

template <int KDIM, bool CONCAT, int ACT>  // ACT: 0 none, 1 silu
__global__ void mma_gemm(const float* __restrict__ A, const float* __restrict__ A2,
                         const float* __restrict__ W0, const float* __restrict__ W1,
                         const float* __restrict__ W2,
                         const float* __restrict__ bias0, const float* __restrict__ bias1,
                         const float* __restrict__ bias2,
                         float* __restrict__ C0, float* __restrict__ C1, float* __restrict__ C2,
                         int M, float scl0) {
    __shared__ __nv_bfloat16 As_hi[BM][LDK];
    __shared__ __nv_bfloat16 As_lo[BM][LDK];
    __shared__ __nv_bfloat16 Bs_hi[BK][LDN];
    __shared__ __nv_bfloat16 Bs_lo[BK][LDN];

    const float* W    = (blockIdx.y == 0) ? W0 : (blockIdx.y == 1) ? W1 : W2;
    const float* bias = (blockIdx.y == 0) ? bias0 : (blockIdx.y == 1) ? bias1 : bias2;
    float* C          = (blockIdx.y == 0) ? C0 : (blockIdx.y == 1) ? C1 : C2;
    const float scl   = (blockIdx.y == 0) ? scl0 : 1.0f;

    const int t = threadIdx.x;
    const int block_m = blockIdx.x * BM;
    const int lane = t & 31;
    const int wid = t >> 5;
    const int warp_m = (wid >> 2) * 64;
    const int warp_n = (wid & 3) * 32;
    const int lg = lane >> 2;
    const int lt = lane & 3;

    float acc[4][4][4];
#pragma unroll
    for (int mi = 0; mi < 4; mi++)
#pragma unroll
        for (int ni = 0; ni < 4; ni++)
#pragma unroll
            for (int r = 0; r < 4; r++) acc[mi][ni][r] = 0.0f;

    for (int k0 = 0; k0 < KDIM; k0 += BK) {
#pragma unroll
        for (int i = 0; i < 4; i++) {
            int idx = t + i * 256;
            int m = idx >> 3;
            int k4 = (idx & 7) * 4;
            int gm = block_m + m;
            float4 v = make_float4(0.f, 0.f, 0.f, 0.f);
            if (gm < M) {
                int gk = k0 + k4;
                if (!CONCAT) v = *(const float4*)(A + (size_t)gm * KDIM + gk);
                else if (gk < HDIM) v = *(const float4*)(A + (size_t)gm * HDIM + gk);
                else {
                    v = *(const float4*)(A2 + (size_t)gm * HDIM + gk - HDIM);
                    float s = g_sm[gm];
                    float inv = (s > 0.0f) ? (1.0f / s) : 0.0f;
                    v.x *= inv; v.y *= inv; v.z *= inv; v.w *= inv;
                }
            }
            __nv_bfloat16 hx, lx, hy, ly, hz, lz, hw, lw;
            split_bf16(v.x, hx, lx); split_bf16(v.y, hy, ly);
            split_bf16(v.z, hz, lz); split_bf16(v.w, hw, lw);
            *(uint2*)&As_hi[m][k4] = make_uint2(pack_bf16(hx, hy), pack_bf16(hz, hw));
            *(uint2*)&As_lo[m][k4] = make_uint2(pack_bf16(lx, ly), pack_bf16(lz, lw));
        }
#pragma unroll
        for (int i = 0; i < 4; i++) {
            int idx = t + i * 256;
            int kk = idx >> 5;
            int n4 = (idx & 31) * 4;
            float4 v = *(const float4*)(W + (size_t)(k0 + kk) * BN + n4);
            __nv_bfloat16 hx, lx, hy, ly, hz, lz, hw, lw;
            split_bf16(v.x, hx, lx); split_bf16(v.y, hy, ly);
            split_bf16(v.z, hz, lz); split_bf16(v.w, hw, lw);
            *(uint2*)&Bs_hi[kk][n4] = make_uint2(pack_bf16(hx, hy), pack_bf16(hz, hw));
            *(uint2*)&Bs_lo[kk][n4] = make_uint2(pack_bf16(lx, ly), pack_bf16(lz, lw));
        }
        __syncthreads();

#pragma unroll
        for (int ks = 0; ks < BK; ks += 16) {
            unsigned ah[4][4], al[4][4], bh[4][2], bl[4][2];
#pragma unroll
            for (int mi = 0; mi < 4; mi++) {
                int r = warp_m + mi * 16 + lg;
                int c = ks + lt * 2;
                ah[mi][0] = *(const unsigned*)&As_hi[r][c];
                ah[mi][1] = *(const unsigned*)&As_hi[r + 8][c];
                ah[mi][2] = *(const unsigned*)&As_hi[r][c + 8];
                ah[mi][3] = *(const unsigned*)&As_hi[r + 8][c + 8];
                al[mi][0] = *(const unsigned*)&As_lo[r][c];
                al[mi][1] = *(const unsigned*)&As_lo[r + 8][c];
                al[mi][2] = *(const unsigned*)&As_lo[r][c + 8];
                al[mi][3] = *(const unsigned*)&As_lo[r + 8][c + 8];
            }
#pragma unroll
            for (int ni = 0; ni < 4; ni++) {
                int n = warp_n + ni * 8 + lg;
                int k = ks + lt * 2;
                bh[ni][0] = pack_bf16(Bs_hi[k][n], Bs_hi[k + 1][n]);
                bh[ni][1] = pack_bf16(Bs_hi[k + 8][n], Bs_hi[k + 9][n]);
                bl[ni][0] = pack_bf16(Bs_lo[k][n], Bs_lo[k + 1][n]);
                bl[ni][1] = pack_bf16(Bs_lo[k + 8][n], Bs_lo[k + 9][n]);
            }
#pragma unroll
            for (int mi = 0; mi < 4; mi++)
#pragma unroll
                for (int ni = 0; ni < 4; ni++) {
                    mma_bf16(acc[mi][ni], ah[mi], bl[ni]);
                    mma_bf16(acc[mi][ni], al[mi], bh[ni]);
                    mma_bf16(acc[mi][ni], ah[mi], bh[ni]);
                }
        }
        __syncthreads();
    }

#pragma unroll
    for (int mi = 0; mi < 4; mi++) {
#pragma unroll
        for (int ni = 0; ni < 4; ni++) {
            int n = warp_n + ni * 8 + lt * 2;
            float b0 = bias[n], b1 = bias[n + 1];
#pragma unroll
            for (int h = 0; h < 2; h++) {
                int gm = block_m + warp_m + mi * 16 + lg + h * 8;
                if (gm >= M) continue;
                float v0 = (acc[mi][ni][2 * h] + b0) * scl;
                float v1 = (acc[mi][ni][2 * h + 1] + b1) * scl;
                if (ACT == 1) {
                    v0 = v0 / (1.0f + expf(-v0));
                    v1 = v1 / (1.0f + expf(-v1));
                }
                *(float2*)(C + (size_t)gm * BN + n) = make_float2(v0, v1);
            }
        }
    }
}

// ---------------- fused edge pass: logit -> exp -> REDG agg + sm (warp per edge) ----------------
// Q pre-scaled by 1/sqrt(H); q.EK+ebias folded into QEK table.
// Normalization deferred: agg accumulates ex*(V+EV); sm accumulates ex.
// Max-subtraction skipped: logits are O(1) here (validated rel_err ~1e-6).
__global__ void edge_fused_kernel(const int* __restrict__ src, const int* __restrict__ tgt,
                                  const int* __restrict__ etype, int E) {
    int e = blockIdx.x * 8 + (threadIdx.x >> 5);
    if (e >= E) return;
    int lane = threadIdx.x & 31;
    int s = src[e], g = tgt[e], ty = etype[e];
    float4 q = ((const float4*)(g_Qn + (size_t)g * HDIM))[lane];
    float4 k = ((const float4*)(g_Kn + (size_t)s * HDIM))[lane];
    float4 v = ((const float4*)(g_Vn + (size_t)s * HDIM))[lane];
    float4 ev = ((const float4*)(g_EV + ty * HDIM))[lane];
    float d = q.x * k.x + q.y * k.y + q.z * k.z + q.w * k.w;
#pragma unroll
    for (int o = 16; o; o >>= 1) d += __shfl_xor_sync(0xffffffffu, d, o);
    float ex = expf(d + g_QEK[g * ETMAX + ty]);   // all lanes hold the same value
    if (lane == 0) atomicAdd(&g_sm[g], ex);
    float* dst = g_agg + (size_t)g * HDIM + lane * 4;
    float a0 = ex * (v.x + ev.x), a1 = ex * (v.y + ev.y);
    float a2 = ex * (v.z + ev.z), a3 = ex * (v.w + ev.w);
    asm volatile("red.global.add.v4.f32 [%0], {%1, %2, %3, %4};"
                 :: "l"(dst), "f"(a0), "f"(a1), "f"(a2), "f"(a3) : "memory");
}

// ---------------- residual + layernorm (warp per node) ----------------
__global__ void residual_ln_kernel(const float* __restrict__ hidden,
                                   const float* __restrict__ gamma,
                                   const float* __restrict__ beta,
                                   float* __restrict__ out, int Nn) {
    int n = blockIdx.x * 8 + (threadIdx.x >> 5);
    if (n >= Nn) return;
    int lane = threadIdx.x & 31;
    float4 h = ((const float4*)(hidden + (size_t)n * HDIM))[lane];
    float4 u = ((const float4*)(g_U + (size_t)n * HDIM))[lane];
    float x0 = h.x + u.x, x1 = h.y + u.y, x2 = h.z + u.z, x3 = h.w + u.w;
    float sum = x0 + x1 + x2 + x3;
#pragma unroll
    for (int o = 16; o; o >>= 1) sum += __shfl_xor_sync(0xffffffffu, sum, o);
    float mu = sum * (1.0f / 128.0f);
    float d0 = x0 - mu, d1 = x1 - mu, d2 = x2 - mu, d3 = x3 - mu;
    float vs = d0 * d0 + d1 * d1 + d2 * d2 + d3 * d3;
#pragma unroll
    for (int o = 16; o; o >>= 1) vs += __shfl_xor_sync(0xffffffffu, vs, o);
    float inv = rsqrtf(vs * (1.0f / 128.0f) + 1e-5f);
    float4 gm = ((const float4*)gamma)[lane];
    float4 bt = ((const float4*)beta)[lane];
    float4 o4;
    o4.x = d0 * inv * gm.x + bt.x;
    o4.y = d1 * inv * gm.y + bt.y;
    o4.z = d2 * inv * gm.z + bt.z;
    o4.w = d3 * inv * gm.w + bt.w;
    ((float4*)(out + (size_t)n * HDIM))[lane] = o4;
}

// ---------------- launch ----------------
extern "C" void kernel_launch(void* const* d_in, const int* in_sizes, int n_in,
                              void* d_out, int out_size) {
    const float* hidden   = (const float*)d_in[0];
    const int*   edge_idx = (const int*)d_in[1];
    const int*   etype    = (const int*)d_in[2];
    const float* edge_emb = (const float*)d_in[3];
    const float* Wq = (const float*)d_in[4];
    const float* bq = (const float*)d_in[5];
    const float* Wk = (const float*)d_in[6];
    const float* bk = (const float*)d_in[7];
    const float* Wv = (const float*)d_in[8];
    const float* bv = (const float*)d_in[9];
    const float* Web = (const float*)d_in[10];
    const float* beb = (const float*)d_in[11];
    const float* W1 = (const float*)d_in[12];
    const float* b1 = (const float*)d_in[13];
    const float* W2 = (const float*)d_in[14];
    const float* b2 = (const float*)d_in[15];
    const float* gamma = (const float*)d_in[16];
    const float* beta  = (const float*)d_in[17];
    float* out = (float*)d_out;

    const int N  = in_sizes[0] / HDIM;   // B=1
    const int E  = in_sizes[2];
    const int ET = in_sizes[3] / HDIM;
    const int* src = edge_idx;           // edge_index[0]
    const int* tgt = edge_idx + E;       // edge_index[1]

    float *pQ, *pK, *pV, *pAgg, *pT, *pU;
    cudaGetSymbolAddress((void**)&pQ, g_Qn);
    cudaGetSymbolAddress((void**)&pK, g_Kn);
    cudaGetSymbolAddress((void**)&pV, g_Vn);
    cudaGetSymbolAddress((void**)&pAgg, g_agg);
    cudaGetSymbolAddress((void**)&pT, g_T);
    cudaGetSymbolAddress((void**)&pU, g_U);

    // 1. init sm / agg
    init_kernel<<<(N * HDIM + 255) / 256, 256>>>(N);

    // 2. edge-type tables (tiny)
    etype_precompute<<<(ET * HDIM + 255) / 256, 256>>>(edge_emb, Wk, Wv, Web, beb, ET);

    // 3. node Q/K/V tables fused (Q pre-scaled by 1/sqrt(H))
    int gemm_blocks = (N + BM - 1) / BM;
    mma_gemm<128, false, 0><<<dim3(gemm_blocks, 3), 256>>>(hidden, nullptr,
                                                           Wq, Wk, Wv, bq, bk, bv,
                                                           pQ, pK, pV, N,
                                                           0.08838834764831845f);

    // 4. QEK table (needs Q + EK)
    qek_kernel<<<(N + 7) / 8, 256>>>(N);

    // 5. fused edge pass: exp(logit) -> REDG agg + sm
    edge_fused_kernel<<<(E + 7) / 8, 256>>>(src, tgt, etype, E);

    // 6. FFN: T = silu([hidden | agg/sm] @ W1 + b1); U = T @ W2 + b2
    mma_gemm<256, true, 1><<<dim3(gemm_blocks, 1), 256>>>(hidden, pAgg,
                                                          W1, W1, W1, b1, b1, b1,
                                                          pT, pT, pT, N, 1.0f);
    mma_gemm<128, false, 0><<<dim3(gemm_blocks, 1), 256>>>(pT, nullptr,
                                                           W2, W2, W2, b2, b2, b2,
                                                           pU, pU, pU, N, 1.0f);

    // 7. residual + layernorm
    residual_ln_kernel<<<(N + 7) / 8, 256>>>(hidden, gamma, beta, out, N);
}

// round 6
// speedup vs baseline: 1.5651x; 1.1864x over previous
#include <cuda_runtime.h>
#include <cuda_bf16.h>
#include <math.h>

// Problem constants (B=1, N=50000, E=600000, H=128, ET=8)
#define NMAX 50000
#define EMAX 600000
#define HDIM 128
#define ETMAX 8

// ---------------- scratch ----------------
__device__ float g_Qp[NMAX * HDIM];     // Q' = scale*q @ Wk^T
__device__ float g_hagg[NMAX * HDIM];   // sum of ex * hidden[src]
__device__ float g_T[NMAX * HDIM];
__device__ float g_U[NMAX * HDIM];
__device__ float g_QEK[NMAX * ETMAX];   // scale*q.(EK[ty]+bk) + ebias[ty]
__device__ float g_exsum[NMAX * ETMAX]; // per (tgt, ty) sum of ex
__device__ float g_wex[NMAX * ETMAX];   // exsum * invsm
__device__ float g_invsm[NMAX];
__device__ float g_EK[ETMAX * HDIM];
__device__ float g_EV[ETMAX * HDIM];
__device__ float g_ebias[ETMAX];
__device__ float g_Wp[HDIM * HDIM];     // scale * Wq @ Wk^T   (row m, col i)
__device__ float g_bp[HDIM];            // scale * bq @ Wk^T
__device__ float g_WqEK[HDIM * ETMAX];  // scale * Wq @ (EK+bk)^T
__device__ float g_cbias[ETMAX];        // scale * bq.(EK+bk) + ebias
__device__ float g_WvW1[HDIM * HDIM];   // Wv @ W1[128:256]
__device__ float g_EVW[ETMAX * HDIM];   // EV @ W1[128:256]
__device__ float g_b1t[HDIM];           // b1 + bv @ W1[128:256]

#define SCALE 0.08838834764831845f  // 1/sqrt(128)

// ---------------- bf16 helpers ----------------
__device__ __forceinline__ unsigned pack_bf16(__nv_bfloat16 lo_k, __nv_bfloat16 hi_k) {
    return ((unsigned)__bfloat16_as_ushort(hi_k) << 16) | (unsigned)__bfloat16_as_ushort(lo_k);
}
__device__ __forceinline__ void split_bf16(float v, __nv_bfloat16& hi, __nv_bfloat16& lo) {
    hi = __float2bfloat16(v);
    lo = __float2bfloat16(v - __bfloat162float(hi));
}
__device__ __forceinline__ void mma_bf16(float c[4], const unsigned a[4], const unsigned b[2]) {
    asm volatile(
        "mma.sync.aligned.m16n8k16.row.col.f32.bf16.bf16.f32 "
        "{%0,%1,%2,%3}, {%4,%5,%6,%7}, {%8,%9}, {%0,%1,%2,%3};"
        : "+f"(c[0]), "+f"(c[1]), "+f"(c[2]), "+f"(c[3])
        : "r"(a[0]), "r"(a[1]), "r"(a[2]), "r"(a[3]), "r"(b[0]), "r"(b[1]));
}

// ---------------- init: hagg=0, exsum=0 ----------------
__global__ void init_kernel(int Nn) {
    int i = blockIdx.x * blockDim.x + threadIdx.x;
    if (i < Nn * HDIM) g_hagg[i] = 0.0f;
    if (i < Nn * ETMAX) g_exsum[i] = 0.0f;
}

// ---------------- EK/EV/ebias ----------------
__global__ void etype_precompute(const float* __restrict__ edge_emb,
                                 const float* __restrict__ Wk,
                                 const float* __restrict__ Wv,
                                 const float* __restrict__ Web,
                                 const float* __restrict__ beb,
                                 int ET) {
    int idx = blockIdx.x * blockDim.x + threadIdx.x;
    if (idx >= ET * HDIM) return;
    int t = idx / HDIM;
    int j = idx % HDIM;
    float sk = 0.0f, sv = 0.0f;
    const float* eh = edge_emb + t * HDIM;
#pragma unroll 8
    for (int k = 0; k < HDIM; k++) {
        float e = eh[k];
        sk = fmaf(e, Wk[k * HDIM + j], sk);
        sv = fmaf(e, Wv[k * HDIM + j], sv);
    }
    g_EK[idx] = sk;
    g_EV[idx] = sv;
    if (j == 0) {
        float s = beb[0];
        for (int k = 0; k < HDIM; k++) s = fmaf(eh[k], Web[k], s);
        g_ebias[t] = s;
    }
}

// ---------------- combined small-matrix precompute ----------------
// outputs (linear index ranges):
//   [0, 16384)          W'[m][i]   = SCALE * dot(Wq[m,:], Wk[i,:])
//   [16384, 16512)      b'[i]      = SCALE * dot(bq, Wk[i,:])
//   [16512, 17536)      WqEK[m][t] = SCALE * dot(Wq[m,:], EK[t,:]+bk)
//   [17536, 17544)      cbias[t]   = SCALE * dot(bq, EK[t,:]+bk) + ebias[t]
//   [17544, 33928)      WvW1[m][n] = sum_k Wv[m][k]*W1[(128+k)][n]
//   [33928, 34952)      EVW[t][n]  = sum_k EV[t][k]*W1[(128+k)][n]
//   [34952, 35080)      b1t[n]     = b1[n] + sum_k bv[k]*W1[(128+k)][n]
__global__ void combo_precompute(const float* __restrict__ Wq, const float* __restrict__ bq,
                                 const float* __restrict__ Wk, const float* __restrict__ bk,
                                 const float* __restrict__ Wv, const float* __restrict__ bv,
                                 const float* __restrict__ W1, const float* __restrict__ b1) {
    int idx = blockIdx.x * blockDim.x + threadIdx.x;
    const float* W1b = W1 + HDIM * HDIM;  // rows 128..255
    if (idx < 16384) {
        int m = idx >> 7, i = idx & 127;
        float s = 0.0f;
#pragma unroll 8
        for (int j = 0; j < HDIM; j++) s = fmaf(Wq[m * HDIM + j], Wk[i * HDIM + j], s);
        g_Wp[m * HDIM + i] = s * SCALE;
    } else if (idx < 16512) {
        int i = idx - 16384;
        float s = 0.0f;
        for (int j = 0; j < HDIM; j++) s = fmaf(bq[j], Wk[i * HDIM + j], s);
        g_bp[i] = s * SCALE;
    } else if (idx < 17536) {
        int r = idx - 16512;
        int m = r >> 3, t = r & 7;
        float s = 0.0f;
#pragma unroll 8
        for (int j = 0; j < HDIM; j++)
            s = fmaf(Wq[m * HDIM + j], g_EK[t * HDIM + j] + bk[j], s);
        g_WqEK[m * ETMAX + t] = s * SCALE;
    } else if (idx < 17544) {
        int t = idx - 17536;
        float s = 0.0f;
        for (int j = 0; j < HDIM; j++) s = fmaf(bq[j], g_EK[t * HDIM + j] + bk[j], s);
        g_cbias[t] = s * SCALE + g_ebias[t];
    } else if (idx < 33928) {
        int r = idx - 17544;
        int m = r >> 7, n = r & 127;
        float s = 0.0f;
#pragma unroll 8
        for (int k = 0; k < HDIM; k++) s = fmaf(Wv[m * HDIM + k], W1b[k * HDIM + n], s);
        g_WvW1[m * HDIM + n] = s;
    } else if (idx < 34952) {
        int r = idx - 33928;
        int t = r >> 7, n = r & 127;
        float s = 0.0f;
#pragma unroll 8
        for (int k = 0; k < HDIM; k++) s = fmaf(g_EV[t * HDIM + k], W1b[k * HDIM + n], s);
        g_EVW[t * HDIM + n] = s;
    } else if (idx < 35080) {
        int n = idx - 34952;
        float s = b1[n];
        for (int k = 0; k < HDIM; k++) s = fmaf(bv[k], W1b[k * HDIM + n], s);
        g_b1t[n] = s;
    }
}

// ---------------- bf16x2 tensor-core GEMM (3-term compensated) ----------------
// MODE 0: plain (FFN2).
// MODE 1: plain + QEK side-output (Q' GEMM; A=hidden, extra 8-col MMA vs WqEK).
// MODE 2: FFN1: A=[hidden | hagg*invsm], W top=W1, bottom=Wb(WvW1),
//         epilogue adds wex@EVW, then silu.
constexpr int BM = 128, BN = 128, BK = 32;
constexpr int LDK = BK + 8;
constexpr int LDN = BN + 8;

template <int KDIM, int MODE>
__global__ void mma_gemm(const float* __restrict__ A, const float* __restrict__ A2,
                         const float* __restrict__ W, const float* __restrict__ Wb,
                         const float* __restrict__ bias,
                         float* __restrict__ C, int M) {
    __shared__ __nv_bfloat16 As_hi[BM][LDK];
    __shared__ __nv_bfloat16 As_lo[BM][LDK];
    __shared__ __nv_bfloat16 Bs_hi[BK][LDN];
    __shared__ __nv_bfloat16 Bs_lo[BK][LDN];
    __shared__ __nv_bfloat16 QEs_hi[BK][8];
    __shared__ __nv_bfloat16 QEs_lo[BK][8];
    __shared__ float evws[ETMAX][HDIM];
    __shared__ float wexs[BM][ETMAX];

    const int t = threadIdx.x;
    const int block_m = blockIdx.x * BM;
    const int lane = t & 31;
    const int wid = t >> 5;
    const int warp_m = (wid >> 2) * 64;
    const int warp_n = (wid & 3) * 32;
    const int lg = lane >> 2;
    const int lt = lane & 3;

    if (MODE == 2) {
        // preload EVW and wex rows for this block (used in epilogue)
        {
            int ty = t >> 5, n4 = (t & 31) * 4;
            *(float4*)&evws[ty][n4] = *(const float4*)(g_EVW + ty * HDIM + n4);
        }
        {
            int r = t >> 1, half = t & 1;
            int gm = block_m + r;
            float4 v = make_float4(0.f, 0.f, 0.f, 0.f);
            if (gm < M) v = *(const float4*)(g_wex + gm * ETMAX + half * 4);
            *(float4*)&wexs[r][half * 4] = v;
        }
    }

    float acc[4][4][4];
#pragma unroll
    for (int mi = 0; mi < 4; mi++)
#pragma unroll
        for (int ni = 0; ni < 4; ni++)
#pragma unroll
            for (int r = 0; r < 4; r++) acc[mi][ni][r] = 0.0f;

    float acc_q[4][4];
    if (MODE == 1) {
#pragma unroll
        for (int mi = 0; mi < 4; mi++)
#pragma unroll
            for (int r = 0; r < 4; r++) acc_q[mi][r] = 0.0f;
    }

    for (int k0 = 0; k0 < KDIM; k0 += BK) {
        // ---- A tile ----
#pragma unroll
        for (int i = 0; i < 4; i++) {
            int idx = t + i * 256;
            int m = idx >> 3;
            int k4 = (idx & 7) * 4;
            int gm = block_m + m;
            float4 v = make_float4(0.f, 0.f, 0.f, 0.f);
            if (gm < M) {
                int gk = k0 + k4;
                if (MODE != 2) v = *(const float4*)(A + (size_t)gm * KDIM + gk);
                else if (gk < HDIM) v = *(const float4*)(A + (size_t)gm * HDIM + gk);
                else {
                    v = *(const float4*)(A2 + (size_t)gm * HDIM + gk - HDIM);
                    float inv = g_invsm[gm];
                    v.x *= inv; v.y *= inv; v.z *= inv; v.w *= inv;
                }
            }
            __nv_bfloat16 hx, lx, hy, ly, hz, lz, hw, lw;
            split_bf16(v.x, hx, lx); split_bf16(v.y, hy, ly);
            split_bf16(v.z, hz, lz); split_bf16(v.w, hw, lw);
            *(uint2*)&As_hi[m][k4] = make_uint2(pack_bf16(hx, hy), pack_bf16(hz, hw));
            *(uint2*)&As_lo[m][k4] = make_uint2(pack_bf16(lx, ly), pack_bf16(lz, lw));
        }
        // ---- B tile ----
#pragma unroll
        for (int i = 0; i < 4; i++) {
            int idx = t + i * 256;
            int kk = idx >> 5;
            int n4 = (idx & 31) * 4;
            int gk = k0 + kk;
            float4 v;
            if (MODE != 2 || gk < HDIM) v = *(const float4*)(W + (size_t)gk * BN + n4);
            else v = *(const float4*)(Wb + (size_t)(gk - HDIM) * BN + n4);
            __nv_bfloat16 hx, lx, hy, ly, hz, lz, hw, lw;
            split_bf16(v.x, hx, lx); split_bf16(v.y, hy, ly);
            split_bf16(v.z, hz, lz); split_bf16(v.w, hw, lw);
            *(uint2*)&Bs_hi[kk][n4] = make_uint2(pack_bf16(hx, hy), pack_bf16(hz, hw));
            *(uint2*)&Bs_lo[kk][n4] = make_uint2(pack_bf16(lx, ly), pack_bf16(lz, lw));
        }
        // ---- WqEK tile (MODE 1) ----
        if (MODE == 1) {
            int kk = t >> 3, ty = t & 7;
            float v = g_WqEK[(k0 + kk) * ETMAX + ty];
            __nv_bfloat16 hi, lo;
            split_bf16(v, hi, lo);
            QEs_hi[kk][ty] = hi;
            QEs_lo[kk][ty] = lo;
        }
        __syncthreads();

#pragma unroll
        for (int ks = 0; ks < BK; ks += 16) {
            unsigned ah[4][4], al[4][4], bh[4][2], bl[4][2];
#pragma unroll
            for (int mi = 0; mi < 4; mi++) {
                int r = warp_m + mi * 16 + lg;
                int c = ks + lt * 2;
                ah[mi][0] = *(const unsigned*)&As_hi[r][c];
                ah[mi][1] = *(const unsigned*)&As_hi[r + 8][c];
                ah[mi][2] = *(const unsigned*)&As_hi[r][c + 8];
                ah[mi][3] = *(const unsigned*)&As_hi[r + 8][c + 8];
                al[mi][0] = *(const unsigned*)&As_lo[r][c];
                al[mi][1] = *(const unsigned*)&As_lo[r + 8][c];
                al[mi][2] = *(const unsigned*)&As_lo[r][c + 8];
                al[mi][3] = *(const unsigned*)&As_lo[r + 8][c + 8];
            }
#pragma unroll
            for (int ni = 0; ni < 4; ni++) {
                int n = warp_n + ni * 8 + lg;
                int k = ks + lt * 2;
                bh[ni][0] = pack_bf16(Bs_hi[k][n], Bs_hi[k + 1][n]);
                bh[ni][1] = pack_bf16(Bs_hi[k + 8][n], Bs_hi[k + 9][n]);
                bl[ni][0] = pack_bf16(Bs_lo[k][n], Bs_lo[k + 1][n]);
                bl[ni][1] = pack_bf16(Bs_lo[k + 8][n], Bs_lo[k + 9][n]);
            }
#pragma unroll
            for (int mi = 0; mi < 4; mi++)
#pragma unroll
                for (int ni = 0; ni < 4; ni++) {
                    mma_bf16(acc[mi][ni], ah[mi], bl[ni]);
                    mma_bf16(acc[mi][ni], al[mi], bh[ni]);
                    mma_bf16(acc[mi][ni], ah[mi], bh[ni]);
                }
            if (MODE == 1 && warp_n == 0) {
                unsigned qh[2], ql[2];
                int k = ks + lt * 2;
                qh[0] = pack_bf16(QEs_hi[k][lg], QEs_hi[k + 1][lg]);
                qh[1] = pack_bf16(QEs_hi[k + 8][lg], QEs_hi[k + 9][lg]);
                ql[0] = pack_bf16(QEs_lo[k][lg], QEs_lo[k + 1][lg]);
                ql[1] = pack_bf16(QEs_lo[k + 8][lg], QEs_lo[k + 9][lg]);
#pragma unroll
                for (int mi = 0; mi < 4; mi++) {
                    mma_bf16(acc_q[mi], ah[mi], ql);
                    mma_bf16(acc_q[mi], al[mi], qh);
                    mma_bf16(acc_q[mi], ah[mi], qh);
                }
            }
        }
        __syncthreads();
    }

    // ---- epilogue ----
#pragma unroll
    for (int mi = 0; mi < 4; mi++) {
#pragma unroll
        for (int ni = 0; ni < 4; ni++) {
            int n = warp_n + ni * 8 + lt * 2;
            float b0 = bias[n], b1 = bias[n + 1];
#pragma unroll
            for (int h = 0; h < 2; h++) {
                int r = warp_m + mi * 16 + lg + h * 8;
                int gm = block_m + r;
                if (gm >= M) continue;
                float v0 = acc[mi][ni][2 * h] + b0;
                float v1 = acc[mi][ni][2 * h + 1] + b1;
                if (MODE == 2) {
#pragma unroll
                    for (int ty = 0; ty < ETMAX; ty++) {
                        float wv = wexs[r][ty];
                        v0 = fmaf(wv, evws[ty][n], v0);
                        v1 = fmaf(wv, evws[ty][n + 1], v1);
                    }
                    v0 = v0 / (1.0f + expf(-v0));
                    v1 = v1 / (1.0f + expf(-v1));
                }
                *(float2*)(C + (size_t)gm * BN + n) = make_float2(v0, v1);
            }
        }
    }

    if (MODE == 1 && warp_n == 0) {
        float cb0 = g_cbias[lt * 2], cb1 = g_cbias[lt * 2 + 1];
#pragma unroll
        for (int mi = 0; mi < 4; mi++)
#pragma unroll
            for (int h = 0; h < 2; h++) {
                int gm = block_m + warp_m + mi * 16 + lg + h * 8;
                if (gm >= M) continue;
                *(float2*)(g_QEK + gm * ETMAX + lt * 2) =
                    make_float2(acc_q[mi][2 * h] + cb0, acc_q[mi][2 * h + 1] + cb1);
            }
    }
}

// ---------------- fused edge pass (warp per edge) ----------------
// ex = exp(Q'[g].hidden[s] + QEK[g][ty]); hagg[g] += ex*hidden[s]; exsum[g][ty] += ex.
__global__ void edge_fused_kernel(const float* __restrict__ hidden,
                                  const int* __restrict__ src, const int* __restrict__ tgt,
                                  const int* __restrict__ etype, int E) {
    int e = blockIdx.x * 8 + (threadIdx.x >> 5);
    if (e >= E) return;
    int lane = threadIdx.x & 31;
    int s = src[e], g = tgt[e], ty = etype[e];
    float4 q = ((const float4*)(g_Qp + (size_t)g * HDIM))[lane];
    float4 h = ((const float4*)(hidden + (size_t)s * HDIM))[lane];
    float d = q.x * h.x + q.y * h.y + q.z * h.z + q.w * h.w;
#pragma unroll
    for (int o = 16; o; o >>= 1) d += __shfl_xor_sync(0xffffffffu, d, o);
    float ex = expf(d + g_QEK[g * ETMAX + ty]);
    if (lane == 0) atomicAdd(&g_exsum[g * ETMAX + ty], ex);
    float* dst = g_hagg + (size_t)g * HDIM + lane * 4;
    asm volatile("red.global.add.v4.f32 [%0], {%1, %2, %3, %4};"
                 :: "l"(dst), "f"(ex * h.x), "f"(ex * h.y), "f"(ex * h.z), "f"(ex * h.w)
                 : "memory");
}

// ---------------- normalize: invsm + wex (thread per node) ----------------
__global__ void normalize_kernel(int Nn) {
    int n = blockIdx.x * blockDim.x + threadIdx.x;
    if (n >= Nn) return;
    float4 a = *(const float4*)(g_exsum + n * ETMAX);
    float4 b = *(const float4*)(g_exsum + n * ETMAX + 4);
    float s = a.x + a.y + a.z + a.w + b.x + b.y + b.z + b.w;
    float inv = (s > 0.0f) ? (1.0f / s) : 0.0f;
    g_invsm[n] = inv;
    *(float4*)(g_wex + n * ETMAX) = make_float4(a.x * inv, a.y * inv, a.z * inv, a.w * inv);
    *(float4*)(g_wex + n * ETMAX + 4) = make_float4(b.x * inv, b.y * inv, b.z * inv, b.w * inv);
}

// ---------------- residual + layernorm (warp per node) ----------------
__global__ void residual_ln_kernel(const float* __restrict__ hidden,
                                   const float* __restrict__ gamma,
                                   const float* __restrict__ beta,
                                   float* __restrict__ out, int Nn) {
    int n = blockIdx.x * 8 + (threadIdx.x >> 5);
    if (n >= Nn) return;
    int lane = threadIdx.x & 31;
    float4 h = ((const float4*)(hidden + (size_t)n * HDIM))[lane];
    float4 u = ((const float4*)(g_U + (size_t)n * HDIM))[lane];
    float x0 = h.x + u.x, x1 = h.y + u.y, x2 = h.z + u.z, x3 = h.w + u.w;
    float sum = x0 + x1 + x2 + x3;
#pragma unroll
    for (int o = 16; o; o >>= 1) sum += __shfl_xor_sync(0xffffffffu, sum, o);
    float mu = sum * (1.0f / 128.0f);
    float d0 = x0 - mu, d1 = x1 - mu, d2 = x2 - mu, d3 = x3 - mu;
    float vs = d0 * d0 + d1 * d1 + d2 * d2 + d3 * d3;
#pragma unroll
    for (int o = 16; o; o >>= 1) vs += __shfl_xor_sync(0xffffffffu, vs, o);
    float inv = rsqrtf(vs * (1.0f / 128.0f) + 1e-5f);
    float4 gm = ((const float4*)gamma)[lane];
    float4 bt = ((const float4*)beta)[lane];
    float4 o4;
    o4.x = d0 * inv * gm.x + bt.x;
    o4.y = d1 * inv * gm.y + bt.y;
    o4.z = d2 * inv * gm.z + bt.z;
    o4.w = d3 * inv * gm.w + bt.w;
    ((float4*)(out + (size_t)n * HDIM))[lane] = o4;
}

// ---------------- launch ----------------
extern "C" void kernel_launch(void* const* d_in, const int* in_sizes, int n_in,
                              void* d_out, int out_size) {
    const float* hidden   = (const float*)d_in[0];
    const int*   edge_idx = (const int*)d_in[1];
    const int*   etype    = (const int*)d_in[2];
    const float* edge_emb = (const float*)d_in[3];
    const float* Wq = (const float*)d_in[4];
    const float* bq = (const float*)d_in[5];
    const float* Wk = (const float*)d_in[6];
    const float* bk = (const float*)d_in[7];
    const float* Wv = (const float*)d_in[8];
    const float* bv = (const float*)d_in[9];
    const float* Web = (const float*)d_in[10];
    const float* beb = (const float*)d_in[11];
    const float* W1 = (const float*)d_in[12];
    const float* b1 = (const float*)d_in[13];
    const float* W2 = (const float*)d_in[14];
    const float* b2 = (const float*)d_in[15];
    const float* gamma = (const float*)d_in[16];
    const float* beta  = (const float*)d_in[17];
    float* out = (float*)d_out;

    const int N  = in_sizes[0] / HDIM;
    const int E  = in_sizes[2];
    const int ET = in_sizes[3] / HDIM;
    const int* src = edge_idx;
    const int* tgt = edge_idx + E;

    float *pQp, *pHagg, *pT, *pU, *pWp, *pbp, *pWvW1, *pb1t;
    cudaGetSymbolAddress((void**)&pQp, g_Qp);
    cudaGetSymbolAddress((void**)&pHagg, g_hagg);
    cudaGetSymbolAddress((void**)&pT, g_T);
    cudaGetSymbolAddress((void**)&pU, g_U);
    cudaGetSymbolAddress((void**)&pWp, g_Wp);
    cudaGetSymbolAddress((void**)&pbp, g_bp);
    cudaGetSymbolAddress((void**)&pWvW1, g_WvW1);
    cudaGetSymbolAddress((void**)&pb1t, g_b1t);

    // 1. zero hagg / exsum
    init_kernel<<<(N * HDIM + 255) / 256, 256>>>(N);

    // 2. EK/EV/ebias, then combined small matrices
    etype_precompute<<<(ET * HDIM + 255) / 256, 256>>>(edge_emb, Wk, Wv, Web, beb, ET);
    combo_precompute<<<(35080 + 255) / 256, 256>>>(Wq, bq, Wk, bk, Wv, bv, W1, b1);

    // 3. Q' GEMM with fused QEK side-output
    int gemm_blocks = (N + BM - 1) / BM;
    mma_gemm<128, 1><<<gemm_blocks, 256>>>(hidden, nullptr, pWp, nullptr, pbp, pQp, N);

    // 4. fused edge pass
    edge_fused_kernel<<<(E + 7) / 8, 256>>>(hidden, src, tgt, etype, E);

    // 5. normalize (invsm, wex)
    normalize_kernel<<<(N + 255) / 256, 256>>>(N);

    // 6. FFN1: silu(hidden@W1top + (hagg*inv)@WvW1 + wex@EVW + b1t)
    mma_gemm<256, 2><<<gemm_blocks, 256>>>(hidden, pHagg, W1, pWvW1, pb1t, pT, N);

    // 7. FFN2
    mma_gemm<128, 0><<<gemm_blocks, 256>>>(pT, nullptr, W2, nullptr, b2, pU, N);

    // 8. residual + layernorm
    residual_ln_kernel<<<(N + 7) / 8, 256>>>(hidden, gamma, beta, out, N);
}

// round 7
// speedup vs baseline: 1.7607x; 1.1250x over previous
#include <cuda_runtime.h>
#include <cuda_bf16.h>
#include <math.h>

// Problem constants (B=1, N=50000, E=600000, H=128, ET=8)
#define NMAX 50000
#define EMAX 600000
#define HDIM 128
#define ETMAX 8

// ---------------- scratch ----------------
__device__ float g_Qp[NMAX * HDIM];     // Q' = scale*q @ Wk^T
__device__ float g_hagg[NMAX * HDIM];   // sum of ex * hidden[src]
__device__ float g_T[NMAX * HDIM];
__device__ float g_U[NMAX * HDIM];
__device__ float g_QEK[NMAX * ETMAX];   // scale*q.(EK[ty]+bk) + ebias[ty]
__device__ float g_exsum[NMAX * ETMAX]; // per (tgt, ty) sum of ex
__device__ float g_wex[NMAX * ETMAX];   // exsum * invsm
__device__ float g_invsm[NMAX];
__device__ float g_EK[ETMAX * HDIM];
__device__ float g_EV[ETMAX * HDIM];
__device__ float g_ebias[ETMAX];
__device__ float g_Wp[HDIM * HDIM];     // scale * Wq @ Wk^T
__device__ float g_bp[HDIM];            // scale * bq @ Wk^T
__device__ float g_WqEK[HDIM * ETMAX];  // scale * Wq @ (EK+bk)^T
__device__ float g_cbias[ETMAX];        // scale * bq.(EK+bk) + ebias
__device__ float g_WvW1[HDIM * HDIM];   // Wv @ W1[128:256]
__device__ float g_EVW[ETMAX * HDIM];   // EV @ W1[128:256]
__device__ float g_b1t[HDIM];           // b1 + bv @ W1[128:256]

#define SCALE 0.08838834764831845f  // 1/sqrt(128)

// ---------------- bf16 helpers ----------------
__device__ __forceinline__ unsigned pack_bf16(__nv_bfloat16 lo_k, __nv_bfloat16 hi_k) {
    return ((unsigned)__bfloat16_as_ushort(hi_k) << 16) | (unsigned)__bfloat16_as_ushort(lo_k);
}
__device__ __forceinline__ void split_bf16(float v, __nv_bfloat16& hi, __nv_bfloat16& lo) {
    hi = __float2bfloat16(v);
    lo = __float2bfloat16(v - __bfloat162float(hi));
}
__device__ __forceinline__ void mma_bf16(float c[4], const unsigned a[4], const unsigned b[2]) {
    asm volatile(
        "mma.sync.aligned.m16n8k16.row.col.f32.bf16.bf16.f32 "
        "{%0,%1,%2,%3}, {%4,%5,%6,%7}, {%8,%9}, {%0,%1,%2,%3};"
        : "+f"(c[0]), "+f"(c[1]), "+f"(c[2]), "+f"(c[3])
        : "r"(a[0]), "r"(a[1]), "r"(a[2]), "r"(a[3]), "r"(b[0]), "r"(b[1]));
}

// ---------------- init: hagg=0, exsum=0 ----------------
__global__ void init_kernel(int Nn) {
    int i = blockIdx.x * blockDim.x + threadIdx.x;
    if (i < Nn * HDIM) g_hagg[i] = 0.0f;
    if (i < Nn * ETMAX) g_exsum[i] = 0.0f;
}

// ---------------- EK/EV/ebias ----------------
__global__ void etype_precompute(const float* __restrict__ edge_emb,
                                 const float* __restrict__ Wk,
                                 const float* __restrict__ Wv,
                                 const float* __restrict__ Web,
                                 const float* __restrict__ beb,
                                 int ET) {
    int idx = blockIdx.x * blockDim.x + threadIdx.x;
    if (idx >= ET * HDIM) return;
    int t = idx / HDIM;
    int j = idx % HDIM;
    float sk = 0.0f, sv = 0.0f;
    const float* eh = edge_emb + t * HDIM;
#pragma unroll 8
    for (int k = 0; k < HDIM; k++) {
        float e = eh[k];
        sk = fmaf(e, Wk[k * HDIM + j], sk);
        sv = fmaf(e, Wv[k * HDIM + j], sv);
    }
    g_EK[idx] = sk;
    g_EV[idx] = sv;
    if (j == 0) {
        float s = beb[0];
        for (int k = 0; k < HDIM; k++) s = fmaf(eh[k], Web[k], s);
        g_ebias[t] = s;
    }
}

// ---------------- combined small-matrix precompute ----------------
__global__ void combo_precompute(const float* __restrict__ Wq, const float* __restrict__ bq,
                                 const float* __restrict__ Wk, const float* __restrict__ bk,
                                 const float* __restrict__ Wv, const float* __restrict__ bv,
                                 const float* __restrict__ W1, const float* __restrict__ b1) {
    int idx = blockIdx.x * blockDim.x + threadIdx.x;
    const float* W1b = W1 + HDIM * HDIM;  // rows 128..255
    if (idx < 16384) {
        int m = idx >> 7, i = idx & 127;
        float s = 0.0f;
#pragma unroll 8
        for (int j = 0; j < HDIM; j++) s = fmaf(Wq[m * HDIM + j], Wk[i * HDIM + j], s);
        g_Wp[m * HDIM + i] = s * SCALE;
    } else if (idx < 16512) {
        int i = idx - 16384;
        float s = 0.0f;
        for (int j = 0; j < HDIM; j++) s = fmaf(bq[j], Wk[i * HDIM + j], s);
        g_bp[i] = s * SCALE;
    } else if (idx < 17536) {
        int r = idx - 16512;
        int m = r >> 3, t = r & 7;
        float s = 0.0f;
#pragma unroll 8
        for (int j = 0; j < HDIM; j++)
            s = fmaf(Wq[m * HDIM + j], g_EK[t * HDIM + j] + bk[j], s);
        g_WqEK[m * ETMAX + t] = s * SCALE;
    } else if (idx < 17544) {
        int t = idx - 17536;
        float s = 0.0f;
        for (int j = 0; j < HDIM; j++) s = fmaf(bq[j], g_EK[t * HDIM + j] + bk[j], s);
        g_cbias[t] = s * SCALE + g_ebias[t];
    } else if (idx < 33928) {
        int r = idx - 17544;
        int m = r >> 7, n = r & 127;
        float s = 0.0f;
#pragma unroll 8
        for (int k = 0; k < HDIM; k++) s = fmaf(Wv[m * HDIM + k], W1b[k * HDIM + n], s);
        g_WvW1[m * HDIM + n] = s;
    } else if (idx < 34952) {
        int r = idx - 33928;
        int t = r >> 7, n = r & 127;
        float s = 0.0f;
#pragma unroll 8
        for (int k = 0; k < HDIM; k++) s = fmaf(g_EV[t * HDIM + k], W1b[k * HDIM + n], s);
        g_EVW[t * HDIM + n] = s;
    } else if (idx < 35080) {
        int n = idx - 34952;
        float s = b1[n];
        for (int k = 0; k < HDIM; k++) s = fmaf(bv[k], W1b[k * HDIM + n], s);
        g_b1t[n] = s;
    }
}

// ---------------- bf16x2 tensor-core GEMM (3-term compensated) ----------------
// BM=64 for occupancy: acc=32 regs/thread, target 2+ CTAs/SM.
// MODE 0: plain (FFN2). MODE 1: + QEK side-output. MODE 2: FFN1 w/ epilogue.
constexpr int BM = 64, BN = 128, BK = 32;
constexpr int LDK = BK + 8;
constexpr int LDN = BN + 8;

template <int KDIM, int MODE>
__global__ void __launch_bounds__(256, 2)
mma_gemm(const float* __restrict__ A, const float* __restrict__ A2,
         const float* __restrict__ W, const float* __restrict__ Wb,
         const float* __restrict__ bias,
         float* __restrict__ C, int M) {
    __shared__ __nv_bfloat16 As_hi[BM][LDK];
    __shared__ __nv_bfloat16 As_lo[BM][LDK];
    __shared__ __nv_bfloat16 Bs_hi[BK][LDN];
    __shared__ __nv_bfloat16 Bs_lo[BK][LDN];
    __shared__ __nv_bfloat16 QEs_hi[BK][8];
    __shared__ __nv_bfloat16 QEs_lo[BK][8];
    __shared__ float evws[ETMAX][HDIM];
    __shared__ float wexs[BM][ETMAX];

    const int t = threadIdx.x;
    const int block_m = blockIdx.x * BM;
    const int lane = t & 31;
    const int wid = t >> 5;
    const int warp_m = (wid >> 2) * 32;   // 0 or 32
    const int warp_n = (wid & 3) * 32;    // 0,32,64,96
    const int lg = lane >> 2;
    const int lt = lane & 3;

    if (MODE == 2) {
        {
            int ty = t >> 5, n4 = (t & 31) * 4;
            *(float4*)&evws[ty][n4] = *(const float4*)(g_EVW + ty * HDIM + n4);
        }
        if (t < 128) {
            int r = t >> 1, half = t & 1;
            int gm = block_m + r;
            float4 v = make_float4(0.f, 0.f, 0.f, 0.f);
            if (gm < M) v = *(const float4*)(g_wex + gm * ETMAX + half * 4);
            *(float4*)&wexs[r][half * 4] = v;
        }
    }

    float acc[2][4][4];
#pragma unroll
    for (int mi = 0; mi < 2; mi++)
#pragma unroll
        for (int ni = 0; ni < 4; ni++)
#pragma unroll
            for (int r = 0; r < 4; r++) acc[mi][ni][r] = 0.0f;

    float acc_q[2][4];
    if (MODE == 1) {
#pragma unroll
        for (int mi = 0; mi < 2; mi++)
#pragma unroll
            for (int r = 0; r < 4; r++) acc_q[mi][r] = 0.0f;
    }

    for (int k0 = 0; k0 < KDIM; k0 += BK) {
        // ---- A tile (64 x 32 floats = 512 float4, 2 per thread) ----
#pragma unroll
        for (int i = 0; i < 2; i++) {
            int idx = t + i * 256;
            int m = idx >> 3;
            int k4 = (idx & 7) * 4;
            int gm = block_m + m;
            float4 v = make_float4(0.f, 0.f, 0.f, 0.f);
            if (gm < M) {
                int gk = k0 + k4;
                if (MODE != 2) v = *(const float4*)(A + (size_t)gm * KDIM + gk);
                else if (gk < HDIM) v = *(const float4*)(A + (size_t)gm * HDIM + gk);
                else {
                    v = *(const float4*)(A2 + (size_t)gm * HDIM + gk - HDIM);
                    float inv = g_invsm[gm];
                    v.x *= inv; v.y *= inv; v.z *= inv; v.w *= inv;
                }
            }
            __nv_bfloat16 hx, lx, hy, ly, hz, lz, hw, lw;
            split_bf16(v.x, hx, lx); split_bf16(v.y, hy, ly);
            split_bf16(v.z, hz, lz); split_bf16(v.w, hw, lw);
            *(uint2*)&As_hi[m][k4] = make_uint2(pack_bf16(hx, hy), pack_bf16(hz, hw));
            *(uint2*)&As_lo[m][k4] = make_uint2(pack_bf16(lx, ly), pack_bf16(lz, lw));
        }
        // ---- B tile (32 x 128 floats = 1024 float4, 4 per thread) ----
#pragma unroll
        for (int i = 0; i < 4; i++) {
            int idx = t + i * 256;
            int kk = idx >> 5;
            int n4 = (idx & 31) * 4;
            int gk = k0 + kk;
            float4 v;
            if (MODE != 2 || gk < HDIM) v = *(const float4*)(W + (size_t)gk * BN + n4);
            else v = *(const float4*)(Wb + (size_t)(gk - HDIM) * BN + n4);
            __nv_bfloat16 hx, lx, hy, ly, hz, lz, hw, lw;
            split_bf16(v.x, hx, lx); split_bf16(v.y, hy, ly);
            split_bf16(v.z, hz, lz); split_bf16(v.w, hw, lw);
            *(uint2*)&Bs_hi[kk][n4] = make_uint2(pack_bf16(hx, hy), pack_bf16(hz, hw));
            *(uint2*)&Bs_lo[kk][n4] = make_uint2(pack_bf16(lx, ly), pack_bf16(lz, lw));
        }
        // ---- WqEK tile (MODE 1) ----
        if (MODE == 1) {
            int kk = t >> 3, ty = t & 7;
            float v = g_WqEK[(k0 + kk) * ETMAX + ty];
            __nv_bfloat16 hi, lo;
            split_bf16(v, hi, lo);
            QEs_hi[kk][ty] = hi;
            QEs_lo[kk][ty] = lo;
        }
        __syncthreads();

#pragma unroll
        for (int ks = 0; ks < BK; ks += 16) {
            unsigned ah[2][4], al[2][4], bh[4][2], bl[4][2];
#pragma unroll
            for (int mi = 0; mi < 2; mi++) {
                int r = warp_m + mi * 16 + lg;
                int c = ks + lt * 2;
                ah[mi][0] = *(const unsigned*)&As_hi[r][c];
                ah[mi][1] = *(const unsigned*)&As_hi[r + 8][c];
                ah[mi][2] = *(const unsigned*)&As_hi[r][c + 8];
                ah[mi][3] = *(const unsigned*)&As_hi[r + 8][c + 8];
                al[mi][0] = *(const unsigned*)&As_lo[r][c];
                al[mi][1] = *(const unsigned*)&As_lo[r + 8][c];
                al[mi][2] = *(const unsigned*)&As_lo[r][c + 8];
                al[mi][3] = *(const unsigned*)&As_lo[r + 8][c + 8];
            }
#pragma unroll
            for (int ni = 0; ni < 4; ni++) {
                int n = warp_n + ni * 8 + lg;
                int k = ks + lt * 2;
                bh[ni][0] = pack_bf16(Bs_hi[k][n], Bs_hi[k + 1][n]);
                bh[ni][1] = pack_bf16(Bs_hi[k + 8][n], Bs_hi[k + 9][n]);
                bl[ni][0] = pack_bf16(Bs_lo[k][n], Bs_lo[k + 1][n]);
                bl[ni][1] = pack_bf16(Bs_lo[k + 8][n], Bs_lo[k + 9][n]);
            }
#pragma unroll
            for (int mi = 0; mi < 2; mi++)
#pragma unroll
                for (int ni = 0; ni < 4; ni++) {
                    mma_bf16(acc[mi][ni], ah[mi], bl[ni]);
                    mma_bf16(acc[mi][ni], al[mi], bh[ni]);
                    mma_bf16(acc[mi][ni], ah[mi], bh[ni]);
                }
            if (MODE == 1 && warp_n == 0) {
                unsigned qh[2], ql[2];
                int k = ks + lt * 2;
                qh[0] = pack_bf16(QEs_hi[k][lg], QEs_hi[k + 1][lg]);
                qh[1] = pack_bf16(QEs_hi[k + 8][lg], QEs_hi[k + 9][lg]);
                ql[0] = pack_bf16(QEs_lo[k][lg], QEs_lo[k + 1][lg]);
                ql[1] = pack_bf16(QEs_lo[k + 8][lg], QEs_lo[k + 9][lg]);
#pragma unroll
                for (int mi = 0; mi < 2; mi++) {
                    mma_bf16(acc_q[mi], ah[mi], ql);
                    mma_bf16(acc_q[mi], al[mi], qh);
                    mma_bf16(acc_q[mi], ah[mi], qh);
                }
            }
        }
        __syncthreads();
    }

    // ---- epilogue ----
#pragma unroll
    for (int mi = 0; mi < 2; mi++) {
#pragma unroll
        for (int ni = 0; ni < 4; ni++) {
            int n = warp_n + ni * 8 + lt * 2;
            float b0 = bias[n], b1 = bias[n + 1];
#pragma unroll
            for (int h = 0; h < 2; h++) {
                int r = warp_m + mi * 16 + lg + h * 8;
                int gm = block_m + r;
                if (gm >= M) continue;
                float v0 = acc[mi][ni][2 * h] + b0;
                float v1 = acc[mi][ni][2 * h + 1] + b1;
                if (MODE == 2) {
#pragma unroll
                    for (int ty = 0; ty < ETMAX; ty++) {
                        float wv = wexs[r][ty];
                        v0 = fmaf(wv, evws[ty][n], v0);
                        v1 = fmaf(wv, evws[ty][n + 1], v1);
                    }
                    v0 = v0 / (1.0f + expf(-v0));
                    v1 = v1 / (1.0f + expf(-v1));
                }
                *(float2*)(C + (size_t)gm * BN + n) = make_float2(v0, v1);
            }
        }
    }

    if (MODE == 1 && warp_n == 0) {
        float cb0 = g_cbias[lt * 2], cb1 = g_cbias[lt * 2 + 1];
#pragma unroll
        for (int mi = 0; mi < 2; mi++)
#pragma unroll
            for (int h = 0; h < 2; h++) {
                int gm = block_m + warp_m + mi * 16 + lg + h * 8;
                if (gm >= M) continue;
                *(float2*)(g_QEK + gm * ETMAX + lt * 2) =
                    make_float2(acc_q[mi][2 * h] + cb0, acc_q[mi][2 * h + 1] + cb1);
            }
    }
}

// ---------------- fused edge pass (warp per edge) ----------------
__global__ void edge_fused_kernel(const float* __restrict__ hidden,
                                  const int* __restrict__ src, const int* __restrict__ tgt,
                                  const int* __restrict__ etype, int E) {
    int e = blockIdx.x * 8 + (threadIdx.x >> 5);
    if (e >= E) return;
    int lane = threadIdx.x & 31;
    int s = src[e], g = tgt[e], ty = etype[e];
    float4 q = ((const float4*)(g_Qp + (size_t)g * HDIM))[lane];
    float4 h = ((const float4*)(hidden + (size_t)s * HDIM))[lane];
    float d = q.x * h.x + q.y * h.y + q.z * h.z + q.w * h.w;
#pragma unroll
    for (int o = 16; o; o >>= 1) d += __shfl_xor_sync(0xffffffffu, d, o);
    float ex = expf(d + g_QEK[g * ETMAX + ty]);
    if (lane == 0) atomicAdd(&g_exsum[g * ETMAX + ty], ex);
    float* dst = g_hagg + (size_t)g * HDIM + lane * 4;
    asm volatile("red.global.add.v4.f32 [%0], {%1, %2, %3, %4};"
                 :: "l"(dst), "f"(ex * h.x), "f"(ex * h.y), "f"(ex * h.z), "f"(ex * h.w)
                 : "memory");
}

// ---------------- normalize: invsm + wex ----------------
__global__ void normalize_kernel(int Nn) {
    int n = blockIdx.x * blockDim.x + threadIdx.x;
    if (n >= Nn) return;
    float4 a = *(const float4*)(g_exsum + n * ETMAX);
    float4 b = *(const float4*)(g_exsum + n * ETMAX + 4);
    float s = a.x + a.y + a.z + a.w + b.x + b.y + b.z + b.w;
    float inv = (s > 0.0f) ? (1.0f / s) : 0.0f;
    g_invsm[n] = inv;
    *(float4*)(g_wex + n * ETMAX) = make_float4(a.x * inv, a.y * inv, a.z * inv, a.w * inv);
    *(float4*)(g_wex + n * ETMAX + 4) = make_float4(b.x * inv, b.y * inv, b.z * inv, b.w * inv);
}

// ---------------- residual + layernorm (warp per node) ----------------
__global__ void residual_ln_kernel(const float* __restrict__ hidden,
                                   const float* __restrict__ gamma,
                                   const float* __restrict__ beta,
                                   float* __restrict__ out, int Nn) {
    int n = blockIdx.x * 8 + (threadIdx.x >> 5);
    if (n >= Nn) return;
    int lane = threadIdx.x & 31;
    float4 h = ((const float4*)(hidden + (size_t)n * HDIM))[lane];
    float4 u = ((const float4*)(g_U + (size_t)n * HDIM))[lane];
    float x0 = h.x + u.x, x1 = h.y + u.y, x2 = h.z + u.z, x3 = h.w + u.w;
    float sum = x0 + x1 + x2 + x3;
#pragma unroll
    for (int o = 16; o; o >>= 1) sum += __shfl_xor_sync(0xffffffffu, sum, o);
    float mu = sum * (1.0f / 128.0f);
    float d0 = x0 - mu, d1 = x1 - mu, d2 = x2 - mu, d3 = x3 - mu;
    float vs = d0 * d0 + d1 * d1 + d2 * d2 + d3 * d3;
#pragma unroll
    for (int o = 16; o; o >>= 1) vs += __shfl_xor_sync(0xffffffffu, vs, o);
    float inv = rsqrtf(vs * (1.0f / 128.0f) + 1e-5f);
    float4 gm = ((const float4*)gamma)[lane];
    float4 bt = ((const float4*)beta)[lane];
    float4 o4;
    o4.x = d0 * inv * gm.x + bt.x;
    o4.y = d1 * inv * gm.y + bt.y;
    o4.z = d2 * inv * gm.z + bt.z;
    o4.w = d3 * inv * gm.w + bt.w;
    ((float4*)(out + (size_t)n * HDIM))[lane] = o4;
}

// ---------------- launch ----------------
extern "C" void kernel_launch(void* const* d_in, const int* in_sizes, int n_in,
                              void* d_out, int out_size) {
    const float* hidden   = (const float*)d_in[0];
    const int*   edge_idx = (const int*)d_in[1];
    const int*   etype    = (const int*)d_in[2];
    const float* edge_emb = (const float*)d_in[3];
    const float* Wq = (const float*)d_in[4];
    const float* bq = (const float*)d_in[5];
    const float* Wk = (const float*)d_in[6];
    const float* bk = (const float*)d_in[7];
    const float* Wv = (const float*)d_in[8];
    const float* bv = (const float*)d_in[9];
    const float* Web = (const float*)d_in[10];
    const float* beb = (const float*)d_in[11];
    const float* W1 = (const float*)d_in[12];
    const float* b1 = (const float*)d_in[13];
    const float* W2 = (const float*)d_in[14];
    const float* b2 = (const float*)d_in[15];
    const float* gamma = (const float*)d_in[16];
    const float* beta  = (const float*)d_in[17];
    float* out = (float*)d_out;

    const int N  = in_sizes[0] / HDIM;
    const int E  = in_sizes[2];
    const int ET = in_sizes[3] / HDIM;
    const int* src = edge_idx;
    const int* tgt = edge_idx + E;

    float *pQp, *pHagg, *pT, *pU, *pWp, *pbp, *pWvW1, *pb1t;
    cudaGetSymbolAddress((void**)&pQp, g_Qp);
    cudaGetSymbolAddress((void**)&pHagg, g_hagg);
    cudaGetSymbolAddress((void**)&pT, g_T);
    cudaGetSymbolAddress((void**)&pU, g_U);
    cudaGetSymbolAddress((void**)&pWp, g_Wp);
    cudaGetSymbolAddress((void**)&pbp, g_bp);
    cudaGetSymbolAddress((void**)&pWvW1, g_WvW1);
    cudaGetSymbolAddress((void**)&pb1t, g_b1t);

    // 1. zero hagg / exsum
    init_kernel<<<(N * HDIM + 255) / 256, 256>>>(N);

    // 2. EK/EV/ebias, then combined small matrices
    etype_precompute<<<(ET * HDIM + 255) / 256, 256>>>(edge_emb, Wk, Wv, Web, beb, ET);
    combo_precompute<<<(35080 + 255) / 256, 256>>>(Wq, bq, Wk, bk, Wv, bv, W1, b1);

    // 3. Q' GEMM with fused QEK side-output
    int gemm_blocks = (N + BM - 1) / BM;
    mma_gemm<128, 1><<<gemm_blocks, 256>>>(hidden, nullptr, pWp, nullptr, pbp, pQp, N);

    // 4. fused edge pass
    edge_fused_kernel<<<(E + 7) / 8, 256>>>(hidden, src, tgt, etype, E);

    // 5. normalize (invsm, wex)
    normalize_kernel<<<(N + 255) / 256, 256>>>(N);

    // 6. FFN1: silu(hidden@W1top + (hagg*inv)@WvW1 + wex@EVW + b1t)
    mma_gemm<256, 2><<<gemm_blocks, 256>>>(hidden, pHagg, W1, pWvW1, pb1t, pT, N);

    // 7. FFN2
    mma_gemm<128, 0><<<gemm_blocks, 256>>>(pT, nullptr, W2, nullptr, b2, pU, N);

    // 8. residual + layernorm
    residual_ln_kernel<<<(N + 7) / 8, 256>>>(hidden, gamma, beta, out, N);
}

// round 8
// speedup vs baseline: 1.7825x; 1.0124x over previous
#include <cuda_runtime.h>
#include <cuda_bf16.h>
#include <math.h>

// Problem constants (B=1, N=50000, E=600000, H=128, ET=8)
#define NMAX 50000
#define EMAX 600000
#define HDIM 128
#define ETMAX 8

// ---------------- scratch ----------------
__device__ float g_Qp[NMAX * HDIM];     // Q' = scale*q @ Wk^T
__device__ float g_hagg[NMAX * HDIM];   // sum of ex * hidden[src]
__device__ float g_T[NMAX * HDIM];
__device__ float g_QEK[NMAX * ETMAX];   // scale*q.(EK[ty]+bk) + ebias[ty]
__device__ float g_exsum[NMAX * ETMAX]; // per (tgt, ty) sum of ex
__device__ float g_wex[NMAX * ETMAX];   // exsum * invsm
__device__ float g_invsm[NMAX];
__device__ float g_EK[ETMAX * HDIM];
__device__ float g_EV[ETMAX * HDIM];
__device__ float g_ebias[ETMAX];
__device__ float g_Wp[HDIM * HDIM];     // scale * Wq @ Wk^T
__device__ float g_bp[HDIM];            // scale * bq @ Wk^T
__device__ float g_WqEK[HDIM * ETMAX];  // scale * Wq @ (EK+bk)^T
__device__ float g_cbias[ETMAX];        // scale * bq.(EK+bk) + ebias
__device__ float g_WvW1[HDIM * HDIM];   // Wv @ W1[128:256]
__device__ float g_EVW[ETMAX * HDIM];   // EV @ W1[128:256]
__device__ float g_b1t[HDIM];           // b1 + bv @ W1[128:256]

#define SCALE 0.08838834764831845f  // 1/sqrt(128)

// ---------------- bf16 helpers ----------------
__device__ __forceinline__ unsigned pack_bf16(__nv_bfloat16 lo_k, __nv_bfloat16 hi_k) {
    return ((unsigned)__bfloat16_as_ushort(hi_k) << 16) | (unsigned)__bfloat16_as_ushort(lo_k);
}
__device__ __forceinline__ void split_bf16(float v, __nv_bfloat16& hi, __nv_bfloat16& lo) {
    hi = __float2bfloat16(v);
    lo = __float2bfloat16(v - __bfloat162float(hi));
}
__device__ __forceinline__ void mma_bf16(float c[4], const unsigned a[4], const unsigned b[2]) {
    asm volatile(
        "mma.sync.aligned.m16n8k16.row.col.f32.bf16.bf16.f32 "
        "{%0,%1,%2,%3}, {%4,%5,%6,%7}, {%8,%9}, {%0,%1,%2,%3};"
        : "+f"(c[0]), "+f"(c[1]), "+f"(c[2]), "+f"(c[3])
        : "r"(a[0]), "r"(a[1]), "r"(a[2]), "r"(a[3]), "r"(b[0]), "r"(b[1]));
}

// ---------------- init: hagg=0, exsum=0 ----------------
__global__ void init_kernel(int Nn) {
    int i = blockIdx.x * blockDim.x + threadIdx.x;
    if (i < Nn * HDIM) g_hagg[i] = 0.0f;
    if (i < Nn * ETMAX) g_exsum[i] = 0.0f;
}

// ---------------- EK/EV/ebias ----------------
__global__ void etype_precompute(const float* __restrict__ edge_emb,
                                 const float* __restrict__ Wk,
                                 const float* __restrict__ Wv,
                                 const float* __restrict__ Web,
                                 const float* __restrict__ beb,
                                 int ET) {
    int idx = blockIdx.x * blockDim.x + threadIdx.x;
    if (idx >= ET * HDIM) return;
    int t = idx / HDIM;
    int j = idx % HDIM;
    float sk = 0.0f, sv = 0.0f;
    const float* eh = edge_emb + t * HDIM;
#pragma unroll 8
    for (int k = 0; k < HDIM; k++) {
        float e = eh[k];
        sk = fmaf(e, Wk[k * HDIM + j], sk);
        sv = fmaf(e, Wv[k * HDIM + j], sv);
    }
    g_EK[idx] = sk;
    g_EV[idx] = sv;
    if (j == 0) {
        float s = beb[0];
        for (int k = 0; k < HDIM; k++) s = fmaf(eh[k], Web[k], s);
        g_ebias[t] = s;
    }
}

// ---------------- combined small-matrix precompute ----------------
__global__ void combo_precompute(const float* __restrict__ Wq, const float* __restrict__ bq,
                                 const float* __restrict__ Wk, const float* __restrict__ bk,
                                 const float* __restrict__ Wv, const float* __restrict__ bv,
                                 const float* __restrict__ W1, const float* __restrict__ b1) {
    int idx = blockIdx.x * blockDim.x + threadIdx.x;
    const float* W1b = W1 + HDIM * HDIM;  // rows 128..255
    if (idx < 16384) {
        int m = idx >> 7, i = idx & 127;
        float s = 0.0f;
#pragma unroll 8
        for (int j = 0; j < HDIM; j++) s = fmaf(Wq[m * HDIM + j], Wk[i * HDIM + j], s);
        g_Wp[m * HDIM + i] = s * SCALE;
    } else if (idx < 16512) {
        int i = idx - 16384;
        float s = 0.0f;
        for (int j = 0; j < HDIM; j++) s = fmaf(bq[j], Wk[i * HDIM + j], s);
        g_bp[i] = s * SCALE;
    } else if (idx < 17536) {
        int r = idx - 16512;
        int m = r >> 3, t = r & 7;
        float s = 0.0f;
#pragma unroll 8
        for (int j = 0; j < HDIM; j++)
            s = fmaf(Wq[m * HDIM + j], g_EK[t * HDIM + j] + bk[j], s);
        g_WqEK[m * ETMAX + t] = s * SCALE;
    } else if (idx < 17544) {
        int t = idx - 17536;
        float s = 0.0f;
        for (int j = 0; j < HDIM; j++) s = fmaf(bq[j], g_EK[t * HDIM + j] + bk[j], s);
        g_cbias[t] = s * SCALE + g_ebias[t];
    } else if (idx < 33928) {
        int r = idx - 17544;
        int m = r >> 7, n = r & 127;
        float s = 0.0f;
#pragma unroll 8
        for (int k = 0; k < HDIM; k++) s = fmaf(Wv[m * HDIM + k], W1b[k * HDIM + n], s);
        g_WvW1[m * HDIM + n] = s;
    } else if (idx < 34952) {
        int r = idx - 33928;
        int t = r >> 7, n = r & 127;
        float s = 0.0f;
#pragma unroll 8
        for (int k = 0; k < HDIM; k++) s = fmaf(g_EV[t * HDIM + k], W1b[k * HDIM + n], s);
        g_EVW[t * HDIM + n] = s;
    } else if (idx < 35080) {
        int n = idx - 34952;
        float s = b1[n];
        for (int k = 0; k < HDIM; k++) s = fmaf(bv[k], W1b[k * HDIM + n], s);
        g_b1t[n] = s;
    }
}

// ---------------- bf16x2 tensor-core GEMM (3-term compensated), BK=64, dynamic smem ----
// MODE 1: Q' GEMM + QEK side-output.
// MODE 2: FFN1 (A=[hidden | hagg*invsm], W top=W1, bottom=WvW1, +wex@EVW, silu).
// MODE 3: FFN2 + fused residual + layernorm (writes final out).
constexpr int BM = 64, BN = 128, BK = 64;
constexpr int LDK = BK + 8;   // 72
constexpr int LDN = BN + 8;   // 136

// dynamic smem layout (bytes):
constexpr int OFF_A_HI = 0;                       // bf16 [64][72] = 9216
constexpr int OFF_A_LO = 9216;
constexpr int OFF_B_HI = 18432;                   // bf16 [64][136] = 17408
constexpr int OFF_B_LO = 35840;
constexpr int OFF_QE_HI = 53248;                  // bf16 [64][8] = 1024 (MODE 1)
constexpr int OFF_QE_LO = 54272;
constexpr int OFF_EVW  = 53248;                   // float [8][128] = 4096 (MODE 2)
constexpr int OFF_WEX  = 57344;                   // float [64][8] = 2048 (MODE 2)
constexpr int SMEM_BYTES = 61440;
// MODE 3 epilogue aliases [0, 32768) as float Us[64][128].

template <int KDIM, int MODE>
__global__ void __launch_bounds__(256, 2)
mma_gemm(const float* __restrict__ A, const float* __restrict__ A2,
         const float* __restrict__ W, const float* __restrict__ Wb,
         const float* __restrict__ bias,
         float* __restrict__ C,
         const float* __restrict__ hidden, const float* __restrict__ gamma,
         const float* __restrict__ beta,
         int M) {
    extern __shared__ char dynsmem[];
    __nv_bfloat16* As_hi = (__nv_bfloat16*)(dynsmem + OFF_A_HI);
    __nv_bfloat16* As_lo = (__nv_bfloat16*)(dynsmem + OFF_A_LO);
    __nv_bfloat16* Bs_hi = (__nv_bfloat16*)(dynsmem + OFF_B_HI);
    __nv_bfloat16* Bs_lo = (__nv_bfloat16*)(dynsmem + OFF_B_LO);
    __nv_bfloat16* QE_hi = (__nv_bfloat16*)(dynsmem + OFF_QE_HI);
    __nv_bfloat16* QE_lo = (__nv_bfloat16*)(dynsmem + OFF_QE_LO);
    float* evws = (float*)(dynsmem + OFF_EVW);
    float* wexs = (float*)(dynsmem + OFF_WEX);
    float* Us   = (float*)dynsmem;

    const int t = threadIdx.x;
    const int block_m = blockIdx.x * BM;
    const int lane = t & 31;
    const int wid = t >> 5;
    const int warp_m = (wid >> 2) * 32;   // 0 or 32
    const int warp_n = (wid & 3) * 32;    // 0,32,64,96
    const int lg = lane >> 2;
    const int lt = lane & 3;

    if (MODE == 2) {
        {
            int ty = t >> 5, n4 = (t & 31) * 4;
            *(float4*)&evws[ty * HDIM + n4] = *(const float4*)(g_EVW + ty * HDIM + n4);
        }
        if (t < 128) {
            int r = t >> 1, half = t & 1;
            int gm = block_m + r;
            float4 v = make_float4(0.f, 0.f, 0.f, 0.f);
            if (gm < M) v = *(const float4*)(g_wex + gm * ETMAX + half * 4);
            *(float4*)&wexs[r * ETMAX + half * 4] = v;
        }
    }

    float acc[2][4][4];
#pragma unroll
    for (int mi = 0; mi < 2; mi++)
#pragma unroll
        for (int ni = 0; ni < 4; ni++)
#pragma unroll
            for (int r = 0; r < 4; r++) acc[mi][ni][r] = 0.0f;

    float acc_q[2][4];
    if (MODE == 1) {
#pragma unroll
        for (int mi = 0; mi < 2; mi++)
#pragma unroll
            for (int r = 0; r < 4; r++) acc_q[mi][r] = 0.0f;
    }

    for (int k0 = 0; k0 < KDIM; k0 += BK) {
        // ---- A tile (64 x 64 floats = 1024 float4, 4 per thread) ----
#pragma unroll
        for (int i = 0; i < 4; i++) {
            int idx = t + i * 256;
            int m = idx >> 4;
            int k4 = (idx & 15) * 4;
            int gm = block_m + m;
            float4 v = make_float4(0.f, 0.f, 0.f, 0.f);
            if (gm < M) {
                int gk = k0 + k4;
                if (MODE != 2) v = *(const float4*)(A + (size_t)gm * KDIM + gk);
                else if (gk < HDIM) v = *(const float4*)(A + (size_t)gm * HDIM + gk);
                else {
                    v = *(const float4*)(A2 + (size_t)gm * HDIM + gk - HDIM);
                    float inv = g_invsm[gm];
                    v.x *= inv; v.y *= inv; v.z *= inv; v.w *= inv;
                }
            }
            __nv_bfloat16 hx, lx, hy, ly, hz, lz, hw, lw;
            split_bf16(v.x, hx, lx); split_bf16(v.y, hy, ly);
            split_bf16(v.z, hz, lz); split_bf16(v.w, hw, lw);
            *(uint2*)&As_hi[m * LDK + k4] = make_uint2(pack_bf16(hx, hy), pack_bf16(hz, hw));
            *(uint2*)&As_lo[m * LDK + k4] = make_uint2(pack_bf16(lx, ly), pack_bf16(lz, lw));
        }
        // ---- B tile (64 x 128 floats = 2048 float4, 8 per thread) ----
#pragma unroll
        for (int i = 0; i < 8; i++) {
            int idx = t + i * 256;
            int kk = idx >> 5;
            int n4 = (idx & 31) * 4;
            int gk = k0 + kk;
            float4 v;
            if (MODE != 2 || gk < HDIM) v = *(const float4*)(W + (size_t)gk * BN + n4);
            else v = *(const float4*)(Wb + (size_t)(gk - HDIM) * BN + n4);
            __nv_bfloat16 hx, lx, hy, ly, hz, lz, hw, lw;
            split_bf16(v.x, hx, lx); split_bf16(v.y, hy, ly);
            split_bf16(v.z, hz, lz); split_bf16(v.w, hw, lw);
            *(uint2*)&Bs_hi[kk * LDN + n4] = make_uint2(pack_bf16(hx, hy), pack_bf16(hz, hw));
            *(uint2*)&Bs_lo[kk * LDN + n4] = make_uint2(pack_bf16(lx, ly), pack_bf16(lz, lw));
        }
        // ---- WqEK tile (MODE 1): 64 x 8 = 512, 2 per thread ----
        if (MODE == 1) {
#pragma unroll
            for (int i = 0; i < 2; i++) {
                int idx = t + i * 256;
                int kk = idx >> 3, ty = idx & 7;
                float v = g_WqEK[(k0 + kk) * ETMAX + ty];
                __nv_bfloat16 hi, lo;
                split_bf16(v, hi, lo);
                QE_hi[kk * 8 + ty] = hi;
                QE_lo[kk * 8 + ty] = lo;
            }
        }
        __syncthreads();

#pragma unroll
        for (int ks = 0; ks < BK; ks += 16) {
            unsigned ah[2][4], al[2][4], bh[4][2], bl[4][2];
#pragma unroll
            for (int mi = 0; mi < 2; mi++) {
                int r = warp_m + mi * 16 + lg;
                int c = ks + lt * 2;
                ah[mi][0] = *(const unsigned*)&As_hi[r * LDK + c];
                ah[mi][1] = *(const unsigned*)&As_hi[(r + 8) * LDK + c];
                ah[mi][2] = *(const unsigned*)&As_hi[r * LDK + c + 8];
                ah[mi][3] = *(const unsigned*)&As_hi[(r + 8) * LDK + c + 8];
                al[mi][0] = *(const unsigned*)&As_lo[r * LDK + c];
                al[mi][1] = *(const unsigned*)&As_lo[(r + 8) * LDK + c];
                al[mi][2] = *(const unsigned*)&As_lo[r * LDK + c + 8];
                al[mi][3] = *(const unsigned*)&As_lo[(r + 8) * LDK + c + 8];
            }
#pragma unroll
            for (int ni = 0; ni < 4; ni++) {
                int n = warp_n + ni * 8 + lg;
                int k = ks + lt * 2;
                bh[ni][0] = pack_bf16(Bs_hi[k * LDN + n], Bs_hi[(k + 1) * LDN + n]);
                bh[ni][1] = pack_bf16(Bs_hi[(k + 8) * LDN + n], Bs_hi[(k + 9) * LDN + n]);
                bl[ni][0] = pack_bf16(Bs_lo[k * LDN + n], Bs_lo[(k + 1) * LDN + n]);
                bl[ni][1] = pack_bf16(Bs_lo[(k + 8) * LDN + n], Bs_lo[(k + 9) * LDN + n]);
            }
#pragma unroll
            for (int mi = 0; mi < 2; mi++)
#pragma unroll
                for (int ni = 0; ni < 4; ni++) {
                    mma_bf16(acc[mi][ni], ah[mi], bl[ni]);
                    mma_bf16(acc[mi][ni], al[mi], bh[ni]);
                    mma_bf16(acc[mi][ni], ah[mi], bh[ni]);
                }
            if (MODE == 1 && warp_n == 0) {
                unsigned qh[2], ql[2];
                int k = ks + lt * 2;
                qh[0] = pack_bf16(QE_hi[k * 8 + lg], QE_hi[(k + 1) * 8 + lg]);
                qh[1] = pack_bf16(QE_hi[(k + 8) * 8 + lg], QE_hi[(k + 9) * 8 + lg]);
                ql[0] = pack_bf16(QE_lo[k * 8 + lg], QE_lo[(k + 1) * 8 + lg]);
                ql[1] = pack_bf16(QE_lo[(k + 8) * 8 + lg], QE_lo[(k + 9) * 8 + lg]);
#pragma unroll
                for (int mi = 0; mi < 2; mi++) {
                    mma_bf16(acc_q[mi], ah[mi], ql);
                    mma_bf16(acc_q[mi], al[mi], qh);
                    mma_bf16(acc_q[mi], ah[mi], qh);
                }
            }
        }
        __syncthreads();
    }

    // ---- epilogue ----
    if (MODE != 3) {
#pragma unroll
        for (int mi = 0; mi < 2; mi++) {
#pragma unroll
            for (int ni = 0; ni < 4; ni++) {
                int n = warp_n + ni * 8 + lt * 2;
                float b0 = bias[n], b1 = bias[n + 1];
#pragma unroll
                for (int h = 0; h < 2; h++) {
                    int r = warp_m + mi * 16 + lg + h * 8;
                    int gm = block_m + r;
                    if (gm >= M) continue;
                    float v0 = acc[mi][ni][2 * h] + b0;
                    float v1 = acc[mi][ni][2 * h + 1] + b1;
                    if (MODE == 2) {
#pragma unroll
                        for (int ty = 0; ty < ETMAX; ty++) {
                            float wv = wexs[r * ETMAX + ty];
                            v0 = fmaf(wv, evws[ty * HDIM + n], v0);
                            v1 = fmaf(wv, evws[ty * HDIM + n + 1], v1);
                        }
                        v0 = v0 / (1.0f + expf(-v0));
                        v1 = v1 / (1.0f + expf(-v1));
                    }
                    *(float2*)(C + (size_t)gm * BN + n) = make_float2(v0, v1);
                }
            }
        }
        if (MODE == 1 && warp_n == 0) {
            float cb0 = g_cbias[lt * 2], cb1 = g_cbias[lt * 2 + 1];
#pragma unroll
            for (int mi = 0; mi < 2; mi++)
#pragma unroll
                for (int h = 0; h < 2; h++) {
                    int gm = block_m + warp_m + mi * 16 + lg + h * 8;
                    if (gm >= M) continue;
                    *(float2*)(g_QEK + gm * ETMAX + lt * 2) =
                        make_float2(acc_q[mi][2 * h] + cb0, acc_q[mi][2 * h + 1] + cb1);
                }
        }
    } else {
        // FFN2 + residual + layernorm fused. Stage U (=acc+bias) in smem.
#pragma unroll
        for (int mi = 0; mi < 2; mi++)
#pragma unroll
            for (int ni = 0; ni < 4; ni++) {
                int n = warp_n + ni * 8 + lt * 2;
                float b0 = bias[n], b1 = bias[n + 1];
#pragma unroll
                for (int h = 0; h < 2; h++) {
                    int r = warp_m + mi * 16 + lg + h * 8;
                    *(float2*)&Us[r * HDIM + n] =
                        make_float2(acc[mi][ni][2 * h] + b0, acc[mi][ni][2 * h + 1] + b1);
                }
            }
        __syncthreads();
        float4 gm4 = ((const float4*)gamma)[lane];
        float4 bt4 = ((const float4*)beta)[lane];
#pragma unroll
        for (int j = 0; j < 8; j++) {
            int r = wid * 8 + j;
            int gm = block_m + r;
            if (gm >= M) continue;
            float4 u = *(const float4*)&Us[r * HDIM + lane * 4];
            float4 hh = *(const float4*)(hidden + (size_t)gm * HDIM + lane * 4);
            float x0 = hh.x + u.x, x1 = hh.y + u.y, x2 = hh.z + u.z, x3 = hh.w + u.w;
            float sum = x0 + x1 + x2 + x3;
#pragma unroll
            for (int o = 16; o; o >>= 1) sum += __shfl_xor_sync(0xffffffffu, sum, o);
            float mu = sum * (1.0f / 128.0f);
            float d0 = x0 - mu, d1 = x1 - mu, d2 = x2 - mu, d3 = x3 - mu;
            float vs = d0 * d0 + d1 * d1 + d2 * d2 + d3 * d3;
#pragma unroll
            for (int o = 16; o; o >>= 1) vs += __shfl_xor_sync(0xffffffffu, vs, o);
            float inv = rsqrtf(vs * (1.0f / 128.0f) + 1e-5f);
            float4 o4;
            o4.x = d0 * inv * gm4.x + bt4.x;
            o4.y = d1 * inv * gm4.y + bt4.y;
            o4.z = d2 * inv * gm4.z + bt4.z;
            o4.w = d3 * inv * gm4.w + bt4.w;
            *(float4*)(C + (size_t)gm * HDIM + lane * 4) = o4;
        }
    }
}

// ---------------- fused edge pass (warp per edge) ----------------
__global__ void edge_fused_kernel(const float* __restrict__ hidden,
                                  const int* __restrict__ src, const int* __restrict__ tgt,
                                  const int* __restrict__ etype, int E) {
    int e = blockIdx.x * 8 + (threadIdx.x >> 5);
    if (e >= E) return;
    int lane = threadIdx.x & 31;
    int s = src[e], g = tgt[e], ty = etype[e];
    float4 q = ((const float4*)(g_Qp + (size_t)g * HDIM))[lane];
    float4 h = ((const float4*)(hidden + (size_t)s * HDIM))[lane];
    float d = q.x * h.x + q.y * h.y + q.z * h.z + q.w * h.w;
#pragma unroll
    for (int o = 16; o; o >>= 1) d += __shfl_xor_sync(0xffffffffu, d, o);
    float ex = expf(d + g_QEK[g * ETMAX + ty]);
    if (lane == 0) atomicAdd(&g_exsum[g * ETMAX + ty], ex);
    float* dst = g_hagg + (size_t)g * HDIM + lane * 4;
    asm volatile("red.global.add.v4.f32 [%0], {%1, %2, %3, %4};"
                 :: "l"(dst), "f"(ex * h.x), "f"(ex * h.y), "f"(ex * h.z), "f"(ex * h.w)
                 : "memory");
}

// ---------------- normalize: invsm + wex ----------------
__global__ void normalize_kernel(int Nn) {
    int n = blockIdx.x * blockDim.x + threadIdx.x;
    if (n >= Nn) return;
    float4 a = *(const float4*)(g_exsum + n * ETMAX);
    float4 b = *(const float4*)(g_exsum + n * ETMAX + 4);
    float s = a.x + a.y + a.z + a.w + b.x + b.y + b.z + b.w;
    float inv = (s > 0.0f) ? (1.0f / s) : 0.0f;
    g_invsm[n] = inv;
    *(float4*)(g_wex + n * ETMAX) = make_float4(a.x * inv, a.y * inv, a.z * inv, a.w * inv);
    *(float4*)(g_wex + n * ETMAX + 4) = make_float4(b.x * inv, b.y * inv, b.z * inv, b.w * inv);
}

// ---------------- launch ----------------
extern "C" void kernel_launch(void* const* d_in, const int* in_sizes, int n_in,
                              void* d_out, int out_size) {
    const float* hidden   = (const float*)d_in[0];
    const int*   edge_idx = (const int*)d_in[1];
    const int*   etype    = (const int*)d_in[2];
    const float* edge_emb = (const float*)d_in[3];
    const float* Wq = (const float*)d_in[4];
    const float* bq = (const float*)d_in[5];
    const float* Wk = (const float*)d_in[6];
    const float* bk = (const float*)d_in[7];
    const float* Wv = (const float*)d_in[8];
    const float* bv = (const float*)d_in[9];
    const float* Web = (const float*)d_in[10];
    const float* beb = (const float*)d_in[11];
    const float* W1 = (const float*)d_in[12];
    const float* b1 = (const float*)d_in[13];
    const float* W2 = (const float*)d_in[14];
    const float* b2 = (const float*)d_in[15];
    const float* gamma = (const float*)d_in[16];
    const float* beta  = (const float*)d_in[17];
    float* out = (float*)d_out;

    const int N  = in_sizes[0] / HDIM;
    const int E  = in_sizes[2];
    const int ET = in_sizes[3] / HDIM;
    const int* src = edge_idx;
    const int* tgt = edge_idx + E;

    float *pQp, *pHagg, *pT, *pWp, *pbp, *pWvW1, *pb1t;
    cudaGetSymbolAddress((void**)&pQp, g_Qp);
    cudaGetSymbolAddress((void**)&pHagg, g_hagg);
    cudaGetSymbolAddress((void**)&pT, g_T);
    cudaGetSymbolAddress((void**)&pWp, g_Wp);
    cudaGetSymbolAddress((void**)&pbp, g_bp);
    cudaGetSymbolAddress((void**)&pWvW1, g_WvW1);
    cudaGetSymbolAddress((void**)&pb1t, g_b1t);

    // allow >48KB dynamic smem (idempotent; safe outside/inside capture)
    cudaFuncSetAttribute((const void*)mma_gemm<128, 1>,
                         cudaFuncAttributeMaxDynamicSharedMemorySize, SMEM_BYTES);
    cudaFuncSetAttribute((const void*)mma_gemm<256, 2>,
                         cudaFuncAttributeMaxDynamicSharedMemorySize, SMEM_BYTES);
    cudaFuncSetAttribute((const void*)mma_gemm<128, 3>,
                         cudaFuncAttributeMaxDynamicSharedMemorySize, SMEM_BYTES);

    // 1. zero hagg / exsum
    init_kernel<<<(N * HDIM + 255) / 256, 256>>>(N);

    // 2. EK/EV/ebias, then combined small matrices
    etype_precompute<<<(ET * HDIM + 255) / 256, 256>>>(edge_emb, Wk, Wv, Web, beb, ET);
    combo_precompute<<<(35080 + 255) / 256, 256>>>(Wq, bq, Wk, bk, Wv, bv, W1, b1);

    // 3. Q' GEMM with fused QEK side-output
    int gemm_blocks = (N + BM - 1) / BM;
    mma_gemm<128, 1><<<gemm_blocks, 256, SMEM_BYTES>>>(
        hidden, nullptr, pWp, nullptr, pbp, pQp, nullptr, nullptr, nullptr, N);

    // 4. fused edge pass
    edge_fused_kernel<<<(E + 7) / 8, 256>>>(hidden, src, tgt, etype, E);

    // 5. normalize (invsm, wex)
    normalize_kernel<<<(N + 255) / 256, 256>>>(N);

    // 6. FFN1: silu(hidden@W1top + (hagg*inv)@WvW1 + wex@EVW + b1t) -> T
    mma_gemm<256, 2><<<gemm_blocks, 256, SMEM_BYTES>>>(
        hidden, pHagg, W1, pWvW1, pb1t, pT, nullptr, nullptr, nullptr, N);

    // 7. FFN2 + residual + layernorm -> out
    mma_gemm<128, 3><<<gemm_blocks, 256, SMEM_BYTES>>>(
        pT, nullptr, W2, nullptr, b2, out, hidden, gamma, beta, N);
}